// round 9
// baseline (speedup 1.0000x reference)
#include <cuda_runtime.h>
#include <cuda_bf16.h>
#include <math.h>
#include <stdint.h>

// ---------------- problem constants ----------------
constexpr int Bb  = 256;
constexpr int Tt  = 64;
constexpr int Aa  = 64;
constexpr int Ee  = 1024;
constexpr int HIDn = 1024;
constexpr int DETn = 2048;
constexpr int STOn = 256;
constexpr int G3  = 3 * DETn;   // 6144

typedef __nv_bfloat16 bf16;

// ---------------- device-global scratch (no allocation allowed) ----------------
__device__ __align__(256) bf16 g_Bhh_hi [G3 * DETn],  g_Bhh_lo [G3 * DETn];
__device__ __align__(256) bf16 g_Bih_hi [G3 * HIDn],  g_Bih_lo [G3 * HIDn];
__device__ __align__(256) bf16 g_Brnn_hi[HIDn * 320], g_Brnn_lo[HIDn * 320];
__device__ __align__(256) bf16 g_Bpo_hi [HIDn * 3072],g_Bpo_lo [HIDn * 3072];
__device__ __align__(256) bf16 g_Bpr_hi [HIDn * DETn],g_Bpr_lo [HIDn * DETn];
__device__ __align__(256) bf16 g_Bpm_hi [512 * HIDn], g_Bpm_lo [512 * HIDn];   // interleaved rows
__device__ __align__(256) bf16 g_Bqm_hi [512 * HIDn], g_Bqm_lo [512 * HIDn];   // interleaved rows
__device__ __align__(256) float g_bpm_int[512], g_bqm_int[512];
__device__ __align__(256) float g_zbias[G3];            // stays zero (zero-initialized)
__device__ __align__(256) bf16 g_obs_hi[Bb * Tt * Ee], g_obs_lo[Bb * Tt * Ee];
__device__ __align__(256) bf16 g_act_hi[Bb * Tt * Aa], g_act_lo[Bb * Tt * Aa];
__device__ __align__(256) bf16 g_zact  [Bb * Aa];      // stays zero
__device__ __align__(256) float g_h   [Bb * DETn];
__device__ __align__(256) bf16  g_h_hi[Bb * DETn], g_h_lo[Bb * DETn];
__device__ __align__(256) bf16  g_z_hi[Bb * STOn], g_z_lo[Bb * STOn];
__device__ __align__(256) bf16  g_rn_hi[Bb * HIDn], g_rn_lo[Bb * HIDn];
__device__ __align__(256) bf16  g_pf_hi[Bb * HIDn], g_pf_lo[Bb * HIDn];
__device__ __align__(256) bf16  g_rf_hi[Bb * HIDn], g_rf_lo[Bb * HIDn];
__device__ __align__(256) float g_gi[Bb * G3], g_gh[Bb * G3], g_gh2[Bb * G3];

// ---------------- helpers ----------------
__device__ __forceinline__ uint32_t smem_u32(const void* p) {
    uint32_t a;
    asm("{ .reg .u64 t; cvta.to.shared.u64 t, %1; cvt.u32.u64 %0, t; }" : "=r"(a) : "l"(p));
    return a;
}
__device__ __forceinline__ void cpa16(uint32_t dst, const void* src) {
    asm volatile("cp.async.cg.shared.global [%0], [%1], 16;" :: "r"(dst), "l"(src) : "memory");
}
__device__ __forceinline__ void ldsm4(uint32_t& r0, uint32_t& r1, uint32_t& r2, uint32_t& r3,
                                      uint32_t a) {
    asm volatile("ldmatrix.sync.aligned.m8n8.x4.shared.b16 {%0,%1,%2,%3}, [%4];"
                 : "=r"(r0), "=r"(r1), "=r"(r2), "=r"(r3) : "r"(a));
}
__device__ __forceinline__ void mmabf(float* c, const uint32_t* a, const uint32_t* b) {
    asm volatile(
        "mma.sync.aligned.m16n8k16.row.col.f32.bf16.bf16.f32 "
        "{%0,%1,%2,%3}, {%4,%5,%6,%7}, {%8,%9}, {%0,%1,%2,%3};"
        : "+f"(c[0]), "+f"(c[1]), "+f"(c[2]), "+f"(c[3])
        : "r"(a[0]), "r"(a[1]), "r"(a[2]), "r"(a[3]), "r"(b[0]), "r"(b[1]));
}
__device__ __forceinline__ void split2(float v, bf16& h, bf16& l) {
    h = __float2bfloat16(v);
    l = __float2bfloat16(v - __bfloat162float(h));
}
__device__ __forceinline__ float softplusf(float x) {
    return (x > 20.f) ? x : log1pf(expf(x));
}

// ---------------- tensor GEMM: C[256,N] = epi([A1|A2] @ B^T + bias), 3-term bf16 split ----
struct TG {
    const bf16 *A1hi, *A1lo, *A2hi, *A2lo;
    const bf16 *Bhi, *Blo;
    const float* bias;
    float* C;            // epi 0
    bf16 *Chi, *Clo;     // epi 1
    float *o_m, *o_s, *o_z;   // epi 2
    const float* eps;         // epi 2 (posterior)
    bf16 *zhi, *zlo;          // epi 2 (posterior)
    long lda1, lda2, ldb, ldo;
    int K1, K, Ntiles, ldc, ldch, epi;
};

constexpr int ROW_B = 80;     // padded smem row (bytes) for 32 bf16
constexpr int NSTAGE = 3;

template<int NT, int BM, int BN, int WRM, int WRN>
__global__ __launch_bounds__(NT, (NT == 256 ? 2 : 1)) void tgemm_kernel(TG p0, TG p1, TG p2) {
    constexpr int NA = (BM / WRM) / 16;
    constexpr int NB = (BN / WRN) / 16;
    constexpr int A_PART = BM * ROW_B;
    constexpr int B_PART = BN * ROW_B;
    constexpr int STAGE  = 2 * (A_PART + B_PART);

    TG p = (blockIdx.z == 0) ? p0 : ((blockIdx.z == 1) ? p1 : p2);
    if ((int)blockIdx.y >= p.Ntiles) return;

    extern __shared__ char smem[];
    const uint32_t sb = smem_u32(smem);
    const int tid = threadIdx.x, wid = tid >> 5, lane = tid & 31;
    const int m0 = blockIdx.x * BM, n0 = blockIdx.y * BN;
    const int wm = (wid % WRM) * (BM / WRM), wn = (wid / WRM) * (BN / WRN);

    auto loadChunk = [&](int c) {
        uint32_t stg = sb + (c % NSTAGE) * STAGE;
        long koff = (long)c * 32;
        const bf16 *ah, *al; long lda;
        if (koff < p.K1) { ah = p.A1hi; al = p.A1lo; lda = p.lda1; }
        else             { ah = p.A2hi; al = p.A2lo; lda = p.lda2; koff -= p.K1; }
        const bf16* a_hi = ah + (long)m0 * lda + koff;
        const bf16* a_lo = al + (long)m0 * lda + koff;
        const bf16* b_hi = p.Bhi + (long)n0 * p.ldb + (long)c * 32;
        const bf16* b_lo = p.Blo + (long)n0 * p.ldb + (long)c * 32;
#pragma unroll
        for (int o = tid; o < (BM + BN) * 4; o += NT) {
            int row = o >> 2, seg = o & 3;
            if (row < BM) {
                cpa16(stg + row * ROW_B + seg * 16,          a_hi + (long)row * lda + seg * 8);
                cpa16(stg + A_PART + row * ROW_B + seg * 16, a_lo + (long)row * lda + seg * 8);
            } else {
                int br = row - BM;
                cpa16(stg + 2 * A_PART + br * ROW_B + seg * 16,
                      b_hi + (long)br * p.ldb + seg * 8);
                cpa16(stg + 2 * A_PART + B_PART + br * ROW_B + seg * 16,
                      b_lo + (long)br * p.ldb + seg * 8);
            }
        }
        asm volatile("cp.async.commit_group;" ::: "memory");
    };

    float acc[NA][2 * NB][4];
#pragma unroll
    for (int i = 0; i < NA; i++)
#pragma unroll
        for (int j = 0; j < 2 * NB; j++)
#pragma unroll
            for (int k = 0; k < 4; k++) acc[i][j][k] = 0.f;

    const int nch = p.K >> 5;
    loadChunk(0);
    loadChunk(1);
    for (int c = 0; c < nch; c++) {
        asm volatile("cp.async.wait_group 1;" ::: "memory");   // chunk c resident
        __syncthreads();                                       // all warps done with c-1
        if (c + 2 < nch) loadChunk(c + 2);                     // overwrites stage of c-1: safe

        const uint32_t stg = sb + (c % NSTAGE) * STAGE;
#pragma unroll
        for (int kk = 0; kk < 2; kk++) {
            uint32_t Ah[NA][4], Al[NA][4], Bh[NB][4], Bl[NB][4];
#pragma unroll
            for (int mi = 0; mi < NA; mi++) {
                int row = wm + 16 * mi + (lane & 15);
                uint32_t ad = stg + row * ROW_B + kk * 32 + ((lane >> 4) << 4);
                ldsm4(Ah[mi][0], Ah[mi][1], Ah[mi][2], Ah[mi][3], ad);
                ldsm4(Al[mi][0], Al[mi][1], Al[mi][2], Al[mi][3], ad + A_PART);
            }
#pragma unroll
            for (int pp = 0; pp < NB; pp++) {
                int row = wn + 16 * pp + ((lane >> 4) << 3) + (lane & 7);
                uint32_t bd = stg + 2 * A_PART + row * ROW_B + kk * 32 + (((lane >> 3) & 1) << 4);
                ldsm4(Bh[pp][0], Bh[pp][1], Bh[pp][2], Bh[pp][3], bd);
                ldsm4(Bl[pp][0], Bl[pp][1], Bl[pp][2], Bl[pp][3], bd + B_PART);
            }
#pragma unroll
            for (int mi = 0; mi < NA; mi++)
#pragma unroll
                for (int pp = 0; pp < NB; pp++)
#pragma unroll
                    for (int tt = 0; tt < 2; tt++) {
                        float* ca = acc[mi][2 * pp + tt];
                        mmabf(ca, Ah[mi], &Bh[pp][2 * tt]);
                        mmabf(ca, Ah[mi], &Bl[pp][2 * tt]);
                        mmabf(ca, Al[mi], &Bh[pp][2 * tt]);
                    }
        }
    }

    // ---- epilogue ----
    const int mg = m0 + wm, ng = n0 + wn;
#pragma unroll
    for (int mi = 0; mi < NA; mi++) {
        int r = mg + 16 * mi + (lane >> 2);
#pragma unroll
        for (int nj = 0; nj < 2 * NB; nj++) {
            int cg = ng + 8 * nj + 2 * (lane & 3);
            float b0 = p.bias[cg], b1 = p.bias[cg + 1];
            float v00 = acc[mi][nj][0] + b0, v01 = acc[mi][nj][1] + b1;
            float v10 = acc[mi][nj][2] + b0, v11 = acc[mi][nj][3] + b1;
            if (p.epi == 1) {
                v00 = fmaxf(v00, 0.f); v01 = fmaxf(v01, 0.f);
                v10 = fmaxf(v10, 0.f); v11 = fmaxf(v11, 0.f);
                __nv_bfloat162 h2, l2;
                split2(v00, h2.x, l2.x); split2(v01, h2.y, l2.y);
                *(__nv_bfloat162*)(p.Chi + (long)r * p.ldch + cg) = h2;
                *(__nv_bfloat162*)(p.Clo + (long)r * p.ldch + cg) = l2;
                split2(v10, h2.x, l2.x); split2(v11, h2.y, l2.y);
                *(__nv_bfloat162*)(p.Chi + (long)(r + 8) * p.ldch + cg) = h2;
                *(__nv_bfloat162*)(p.Clo + (long)(r + 8) * p.ldch + cg) = l2;
            } else if (p.epi == 0) {
                float2 f2;
                f2.x = v00; f2.y = v01;
                *(float2*)(p.C + (long)r * p.ldc + cg) = f2;
                f2.x = v10; f2.y = v11;
                *(float2*)(p.C + (long)(r + 8) * p.ldc + cg) = f2;
            } else {
                int j = cg >> 1;
#pragma unroll
                for (int hh = 0; hh < 2; hh++) {
                    int rr = r + 8 * hh;
                    float mean = hh ? v10 : v00;
                    float sraw = hh ? v11 : v01;
                    float s = softplusf(sraw) + 0.1f;
                    long o = (long)rr * p.ldo + j;
                    p.o_m[o] = mean;
                    p.o_s[o] = s;
                    if (p.o_z) {
                        float zv = fmaf(s, p.eps[o], mean);
                        p.o_z[o] = zv;
                        split2(zv, p.zhi[rr * STOn + j], p.zlo[rr * STOn + j]);
                    }
                }
            }
        }
    }
}

constexpr int SMEM_BIG   = NSTAGE * 2 * (128 * ROW_B + 128 * ROW_B);  // 122880 (1 CTA/SM)
constexpr int SMEM_SMALL = NSTAGE * 2 * (64 * ROW_B + 64 * ROW_B);    // 61440  (2 CTA/SM)

// ---------------- GRU gate combine (gh = g_gh + g_gh2 split-K partials) ----------------
__global__ __launch_bounds__(256) void gru_kernel(float* __restrict__ hout) {
    int idx = blockIdx.x * blockDim.x + threadIdx.x;
    int b = idx >> 9;
    int d = (idx & 511) << 2;
    const float* gi  = g_gi  + (long)b * G3 + d;
    const float* gh  = g_gh  + (long)b * G3 + d;
    const float* gh2 = g_gh2 + (long)b * G3 + d;
    float4 ir  = *(const float4*)(gi);
    float4 iu  = *(const float4*)(gi + DETn);
    float4 in_ = *(const float4*)(gi + 2 * DETn);
    float4 hr  = *(const float4*)(gh);
    float4 hu  = *(const float4*)(gh + DETn);
    float4 hn  = *(const float4*)(gh + 2 * DETn);
    float4 hr2 = *(const float4*)(gh2);
    float4 hu2 = *(const float4*)(gh2 + DETn);
    float4 hn2 = *(const float4*)(gh2 + 2 * DETn);
    hr.x += hr2.x; hr.y += hr2.y; hr.z += hr2.z; hr.w += hr2.w;
    hu.x += hu2.x; hu.y += hu2.y; hu.z += hu2.z; hu.w += hu2.w;
    hn.x += hn2.x; hn.y += hn2.y; hn.z += hn2.z; hn.w += hn2.w;
    float4 hp  = *(const float4*)(g_h + (long)b * DETn + d);
    float4 hs;
#define GRUC(X) { \
    float r = 1.f / (1.f + expf(-(ir.X + hr.X))); \
    float u = 1.f / (1.f + expf(-(iu.X + hu.X))); \
    float n = tanhf(in_.X + r * hn.X);            \
    hs.X = (1.f - u) * n + u * hp.X; }
    GRUC(x) GRUC(y) GRUC(z) GRUC(w)
#undef GRUC
    *(float4*)(g_h + (long)b * DETn + d) = hs;
    *(float4*)(hout + (long)b * (Tt * DETn) + d) = hs;
    long o = (long)b * DETn + d;
#pragma unroll
    for (int j = 0; j < 4; j++) {
        float v = (&hs.x)[j];
        split2(v, g_h_hi[o + j], g_h_lo[o + j]);
    }
}

// ---------------- merged prep: zero + elementwise splits + bias interleave ----------------
struct SplitJob { const float* src; bf16* hi; bf16* lo; long n; };

__global__ __launch_bounds__(256) void prep_split_kernel(
    SplitJob j0, SplitJob j1, SplitJob j2, SplitJob j3,
    const float* bpm, const float* bqm) {
    long stride = (long)gridDim.x * blockDim.x;
    long gt = (long)blockIdx.x * blockDim.x + threadIdx.x;
    for (long i = gt; i < Bb * DETn; i += stride) {
        g_h[i] = 0.f;
        g_h_hi[i] = __float2bfloat16(0.f);
        g_h_lo[i] = __float2bfloat16(0.f);
    }
    for (long i = gt; i < Bb * STOn; i += stride) {
        g_z_hi[i] = __float2bfloat16(0.f);
        g_z_lo[i] = __float2bfloat16(0.f);
    }
    for (long i = gt; i < 512; i += stride) {
        int c = (int)(i >> 1) + ((int)i & 1) * 256;
        g_bpm_int[i] = bpm[c];
        g_bqm_int[i] = bqm[c];
    }
    SplitJob jobs[4] = {j0, j1, j2, j3};
#pragma unroll
    for (int jj = 0; jj < 4; jj++) {
        SplitJob j = jobs[jj];
        for (long i = gt; i < j.n; i += stride)
            split2(j.src[i], j.hi[i], j.lo[i]);
    }
}

// ---------------- merged prep: transposed splits (optionally column-interleaved) --------
struct TJob { const float* src; bf16* hi; bf16* lo; int R, C, tileEnd, ilv; };

__global__ __launch_bounds__(256) void prep_tsplit_kernel(
    TJob a, TJob b, TJob c, TJob d, TJob e) {
    __shared__ float t[32][33];
    int bid = blockIdx.x;
    TJob j; int tileBase;
    if      (bid < a.tileEnd) { j = a; tileBase = 0; }
    else if (bid < b.tileEnd) { j = b; tileBase = a.tileEnd; }
    else if (bid < c.tileEnd) { j = c; tileBase = b.tileEnd; }
    else if (bid < d.tileEnd) { j = d; tileBase = c.tileEnd; }
    else                      { j = e; tileBase = d.tileEnd; }
    int tile = bid - tileBase;
    int tiles_x = j.C / 32;
    int c0 = (tile % tiles_x) * 32;
    int r0 = (tile / tiles_x) * 32;
    int tx = threadIdx.x & 31, ty = threadIdx.x >> 5;
    for (int i = ty; i < 32; i += 8)
        t[i][tx] = j.src[(long)(r0 + i) * j.C + c0 + tx];
    __syncthreads();
    for (int i = ty; i < 32; i += 8) {
        float v = t[tx][i];
        int cidx = c0 + i;
        int drow = j.ilv ? ((cidx < 256) ? 2 * cidx : 2 * (cidx - 256) + 1) : cidx;
        long o = (long)drow * j.R + r0 + tx;
        split2(v, j.hi[o], j.lo[o]);
    }
}

// ---------------- host orchestration ----------------
static void* sym(const void* s) { void* p; cudaGetSymbolAddress(&p, s); return p; }

extern "C" void kernel_launch(void* const* d_in, const int* in_sizes, int n_in,
                              void* d_out, int out_size) {
    const float* obs        = (const float*)d_in[0];
    const float* actions    = (const float*)d_in[1];
    const float* noise      = (const float*)d_in[4];
    const float* W_rnn      = (const float*)d_in[5];
    const float* b_rnn      = (const float*)d_in[6];
    const float* Wih        = (const float*)d_in[7];
    const float* Whh        = (const float*)d_in[8];
    const float* bih        = (const float*)d_in[9];
    const float* bhh        = (const float*)d_in[10];
    const float* W_post_in  = (const float*)d_in[11];
    const float* b_post_in  = (const float*)d_in[12];
    const float* W_post_ms  = (const float*)d_in[13];
    const float* b_post_ms  = (const float*)d_in[14];
    const float* W_prior_in = (const float*)d_in[15];
    const float* b_prior_in = (const float*)d_in[16];
    const float* W_prior_ms = (const float*)d_in[17];
    const float* b_prior_ms = (const float*)d_in[18];
    float* out = (float*)d_out;

    cudaFuncSetAttribute(tgemm_kernel<512, 128, 128, 4, 4>,
                         cudaFuncAttributeMaxDynamicSharedMemorySize, SMEM_BIG);
    cudaFuncSetAttribute(tgemm_kernel<256, 64, 64, 2, 4>,
                         cudaFuncAttributeMaxDynamicSharedMemorySize, SMEM_SMALL);

    bf16 *Bhh_hi = (bf16*)sym(g_Bhh_hi), *Bhh_lo = (bf16*)sym(g_Bhh_lo);
    bf16 *Bih_hi = (bf16*)sym(g_Bih_hi), *Bih_lo = (bf16*)sym(g_Bih_lo);
    bf16 *Brnn_hi = (bf16*)sym(g_Brnn_hi), *Brnn_lo = (bf16*)sym(g_Brnn_lo);
    bf16 *Bpo_hi = (bf16*)sym(g_Bpo_hi), *Bpo_lo = (bf16*)sym(g_Bpo_lo);
    bf16 *Bpr_hi = (bf16*)sym(g_Bpr_hi), *Bpr_lo = (bf16*)sym(g_Bpr_lo);
    bf16 *Bpm_hi = (bf16*)sym(g_Bpm_hi), *Bpm_lo = (bf16*)sym(g_Bpm_lo);
    bf16 *Bqm_hi = (bf16*)sym(g_Bqm_hi), *Bqm_lo = (bf16*)sym(g_Bqm_lo);
    float *bpm_i = (float*)sym(g_bpm_int), *bqm_i = (float*)sym(g_bqm_int);
    float *zbias = (float*)sym(g_zbias);
    bf16 *obs_hi = (bf16*)sym(g_obs_hi), *obs_lo = (bf16*)sym(g_obs_lo);
    bf16 *act_hi = (bf16*)sym(g_act_hi), *act_lo = (bf16*)sym(g_act_lo);
    bf16 *zact   = (bf16*)sym(g_zact);
    bf16 *h_hi = (bf16*)sym(g_h_hi), *h_lo = (bf16*)sym(g_h_lo);
    bf16 *z_hi = (bf16*)sym(g_z_hi), *z_lo = (bf16*)sym(g_z_lo);
    bf16 *rn_hi = (bf16*)sym(g_rn_hi), *rn_lo = (bf16*)sym(g_rn_lo);
    bf16 *pf_hi = (bf16*)sym(g_pf_hi), *pf_lo = (bf16*)sym(g_pf_lo);
    bf16 *rf_hi = (bf16*)sym(g_rf_hi), *rf_lo = (bf16*)sym(g_rf_lo);
    float *gi_p = (float*)sym(g_gi), *gh_p = (float*)sym(g_gh), *gh2_p = (float*)sym(g_gh2);

    float* out_h  = out;
    float* out_z  = out_h  + (long)Bb * Tt * DETn;
    float* out_pm = out_z  + (long)Bb * Tt * STOn;
    float* out_ps = out_pm + (long)Bb * Tt * STOn;
    float* out_qm = out_ps + (long)Bb * Tt * STOn;
    float* out_qs = out_qm + (long)Bb * Tt * STOn;

    // ---- prep (2 launches) ----
    {
        SplitJob s0 = {Whh,     Bhh_hi, Bhh_lo, (long)G3 * DETn};
        SplitJob s1 = {Wih,     Bih_hi, Bih_lo, (long)G3 * HIDn};
        SplitJob s2 = {obs,     obs_hi, obs_lo, (long)Bb * Tt * Ee};
        SplitJob s3 = {actions, act_hi, act_lo, (long)Bb * Tt * Aa};
        prep_split_kernel<<<2048, 256>>>(s0, s1, s2, s3, b_post_ms, b_prior_ms);

        int t0 = (320 / 32) * (HIDn / 32);
        int t1 = t0 + (3072 / 32) * (HIDn / 32);
        int t2 = t1 + (DETn / 32) * (HIDn / 32);
        int t3 = t2 + (HIDn / 32) * (512 / 32);
        int t4 = t3 + (HIDn / 32) * (512 / 32);
        TJob a = {W_rnn,      Brnn_hi, Brnn_lo, 320,  HIDn, t0, 0};
        TJob b = {W_post_in,  Bpo_hi,  Bpo_lo,  3072, HIDn, t1, 0};
        TJob c = {W_prior_in, Bpr_hi,  Bpr_lo,  DETn, HIDn, t2, 0};
        TJob d = {W_post_ms,  Bpm_hi,  Bpm_lo,  HIDn, 512,  t3, 1};
        TJob e = {W_prior_ms, Bqm_hi,  Bqm_lo,  HIDn, 512,  t4, 1};
        prep_tsplit_kernel<<<t4, 256>>>(a, b, c, d, e);
    }

    for (int t = 0; t < Tt; t++) {
        // L1: rnn_in = relu([z_prev | a_prev] @ W_rnn + b) -> rn hi/lo
        TG prnn = {};
        prnn.A1hi = z_hi; prnn.A1lo = z_lo; prnn.lda1 = STOn; prnn.K1 = STOn;
        if (t > 0) { prnn.A2hi = act_hi + (long)(t - 1) * Aa; prnn.A2lo = act_lo + (long)(t - 1) * Aa; prnn.lda2 = (long)Tt * Aa; }
        else       { prnn.A2hi = zact; prnn.A2lo = zact; prnn.lda2 = Aa; }
        prnn.Bhi = Brnn_hi; prnn.Blo = Brnn_lo; prnn.ldb = 320;
        prnn.bias = b_rnn; prnn.K = 320; prnn.Ntiles = HIDn / 64;
        prnn.epi = 1; prnn.Chi = rn_hi; prnn.Clo = rn_lo; prnn.ldch = HIDn;
        tgemm_kernel<256, 64, 64, 2, 4><<<dim3(4, HIDn / 64, 1), 256, SMEM_SMALL>>>(prnn, prnn, prnn);

        // L2 split-K: z0: gh_half0 (K 0:1024, bias) ; z1: gh_half1 (K 1024:2048, zero bias) ;
        //             z2: gi (K=1024).  288 equal 128x128x1024 tiles -> 2 near-full waves.
        TG pg0 = {};
        pg0.A1hi = h_hi; pg0.A1lo = h_lo; pg0.lda1 = DETn; pg0.K1 = 1024;
        pg0.Bhi = Bhh_hi; pg0.Blo = Bhh_lo; pg0.ldb = DETn;
        pg0.bias = bhh; pg0.K = 1024; pg0.Ntiles = G3 / 128;
        pg0.epi = 0; pg0.C = gh_p; pg0.ldc = G3;
        TG pg1 = {};
        pg1.A1hi = h_hi + 1024; pg1.A1lo = h_lo + 1024; pg1.lda1 = DETn; pg1.K1 = 1024;
        pg1.Bhi = Bhh_hi + 1024; pg1.Blo = Bhh_lo + 1024; pg1.ldb = DETn;
        pg1.bias = zbias; pg1.K = 1024; pg1.Ntiles = G3 / 128;
        pg1.epi = 0; pg1.C = gh2_p; pg1.ldc = G3;
        TG pgi = {};
        pgi.A1hi = rn_hi; pgi.A1lo = rn_lo; pgi.lda1 = HIDn; pgi.K1 = HIDn;
        pgi.Bhi = Bih_hi; pgi.Blo = Bih_lo; pgi.ldb = HIDn;
        pgi.bias = bih; pgi.K = HIDn; pgi.Ntiles = G3 / 128;
        pgi.epi = 0; pgi.C = gi_p; pgi.ldc = G3;
        tgemm_kernel<512, 128, 128, 4, 4><<<dim3(2, G3 / 128, 3), 512, SMEM_BIG>>>(pg0, pg1, pgi);

        // L3: GRU elementwise -> h
        gru_kernel<<<(Bb * DETn / 4) / 256, 256>>>(out_h + (long)t * DETn);

        // L4: z0: pf = relu([h|obs] @ Wpost_in + b) ; z1: rf = relu(h @ Wprior_in + b)
        TG ppo = {};
        ppo.A1hi = h_hi; ppo.A1lo = h_lo; ppo.lda1 = DETn; ppo.K1 = DETn;
        ppo.A2hi = obs_hi + (long)t * Ee; ppo.A2lo = obs_lo + (long)t * Ee; ppo.lda2 = (long)Tt * Ee;
        ppo.Bhi = Bpo_hi; ppo.Blo = Bpo_lo; ppo.ldb = 3072;
        ppo.bias = b_post_in; ppo.K = 3072; ppo.Ntiles = HIDn / 64;
        ppo.epi = 1; ppo.Chi = pf_hi; ppo.Clo = pf_lo; ppo.ldch = HIDn;
        TG ppr = {};
        ppr.A1hi = h_hi; ppr.A1lo = h_lo; ppr.lda1 = DETn; ppr.K1 = DETn;
        ppr.Bhi = Bpr_hi; ppr.Blo = Bpr_lo; ppr.ldb = DETn;
        ppr.bias = b_prior_in; ppr.K = DETn; ppr.Ntiles = HIDn / 64;
        ppr.epi = 1; ppr.Chi = rf_hi; ppr.Clo = rf_lo; ppr.ldch = HIDn;
        tgemm_kernel<256, 64, 64, 2, 4><<<dim3(4, HIDn / 64, 2), 256, SMEM_SMALL>>>(ppo, ppr, ppr);

        // L5 (fused with finalize): interleaved ms heads; posterior also rsamples z
        TG qpm = {};
        qpm.A1hi = pf_hi; qpm.A1lo = pf_lo; qpm.lda1 = HIDn; qpm.K1 = HIDn;
        qpm.Bhi = Bpm_hi; qpm.Blo = Bpm_lo; qpm.ldb = HIDn;
        qpm.bias = bpm_i; qpm.K = HIDn; qpm.Ntiles = 512 / 64;
        qpm.epi = 2; qpm.ldo = (long)Tt * STOn;
        qpm.o_m = out_pm + (long)t * STOn; qpm.o_s = out_ps + (long)t * STOn;
        qpm.o_z = out_z + (long)t * STOn; qpm.eps = noise + (long)t * STOn;
        qpm.zhi = z_hi; qpm.zlo = z_lo;
        TG qqm = {};
        qqm.A1hi = rf_hi; qqm.A1lo = rf_lo; qqm.lda1 = HIDn; qqm.K1 = HIDn;
        qqm.Bhi = Bqm_hi; qqm.Blo = Bqm_lo; qqm.ldb = HIDn;
        qqm.bias = bqm_i; qqm.K = HIDn; qqm.Ntiles = 512 / 64;
        qqm.epi = 2; qqm.ldo = (long)Tt * STOn;
        qqm.o_m = out_qm + (long)t * STOn; qqm.o_s = out_qs + (long)t * STOn;
        qqm.o_z = nullptr; qqm.eps = nullptr; qqm.zhi = nullptr; qqm.zlo = nullptr;
        tgemm_kernel<256, 64, 64, 2, 4><<<dim3(4, 512 / 64, 2), 256, SMEM_SMALL>>>(qpm, qqm, qqm);
    }
}

// round 10
// speedup vs baseline: 1.1005x; 1.1005x over previous
#include <cuda_runtime.h>
#include <cuda_bf16.h>
#include <math.h>
#include <stdint.h>

// ---------------- problem constants ----------------
constexpr int Bb  = 256;
constexpr int Tt  = 64;
constexpr int Aa  = 64;
constexpr int Ee  = 1024;
constexpr int HIDn = 1024;
constexpr int DETn = 2048;
constexpr int STOn = 256;
constexpr int G3  = 3 * DETn;   // 6144

typedef __nv_bfloat16 bf16;

// ---------------- device-global scratch (no allocation allowed) ----------------
__device__ __align__(256) bf16 g_Bhh_hi [G3 * DETn],  g_Bhh_lo [G3 * DETn];
__device__ __align__(256) bf16 g_Bih_hi [G3 * HIDn],  g_Bih_lo [G3 * HIDn];
__device__ __align__(256) bf16 g_Brnn_hi[HIDn * 320], g_Brnn_lo[HIDn * 320];
__device__ __align__(256) bf16 g_Bpo_hi [HIDn * 3072],g_Bpo_lo [HIDn * 3072];
__device__ __align__(256) bf16 g_Bpr_hi [HIDn * DETn],g_Bpr_lo [HIDn * DETn];
__device__ __align__(256) bf16 g_Bpm_hi [512 * HIDn], g_Bpm_lo [512 * HIDn];   // interleaved rows
__device__ __align__(256) bf16 g_Bqm_hi [512 * HIDn], g_Bqm_lo [512 * HIDn];   // interleaved rows
__device__ __align__(256) float g_bpm_int[512], g_bqm_int[512];
__device__ __align__(256) float g_zbias[G3];            // stays zero (zero-initialized)
__device__ __align__(256) bf16 g_obs_hi[Bb * Tt * Ee], g_obs_lo[Bb * Tt * Ee];
__device__ __align__(256) bf16 g_act_hi[Bb * Tt * Aa], g_act_lo[Bb * Tt * Aa];
__device__ __align__(256) bf16 g_zact  [Bb * Aa];      // stays zero
__device__ __align__(256) float g_h   [Bb * DETn];
__device__ __align__(256) bf16  g_h_hi[Bb * DETn], g_h_lo[Bb * DETn];
__device__ __align__(256) bf16  g_z_hi[Bb * STOn], g_z_lo[Bb * STOn];
__device__ __align__(256) bf16  g_rn_hi[Bb * HIDn], g_rn_lo[Bb * HIDn];
__device__ __align__(256) bf16  g_pf_hi[Bb * HIDn], g_pf_lo[Bb * HIDn];
__device__ __align__(256) bf16  g_rf_hi[Bb * HIDn], g_rf_lo[Bb * HIDn];
__device__ __align__(256) float g_gi[Bb * G3], g_gh[Bb * G3], g_gh2[Bb * G3];
__device__ __align__(256) float g_pfr0[Bb * HIDn], g_pfr1[Bb * HIDn];
__device__ __align__(256) float g_rfr0[Bb * HIDn], g_rfr1[Bb * HIDn];

// ---------------- helpers ----------------
__device__ __forceinline__ uint32_t smem_u32(const void* p) {
    uint32_t a;
    asm("{ .reg .u64 t; cvta.to.shared.u64 t, %1; cvt.u32.u64 %0, t; }" : "=r"(a) : "l"(p));
    return a;
}
__device__ __forceinline__ void cpa16(uint32_t dst, const void* src) {
    asm volatile("cp.async.cg.shared.global [%0], [%1], 16;" :: "r"(dst), "l"(src) : "memory");
}
__device__ __forceinline__ void ldsm4(uint32_t& r0, uint32_t& r1, uint32_t& r2, uint32_t& r3,
                                      uint32_t a) {
    asm volatile("ldmatrix.sync.aligned.m8n8.x4.shared.b16 {%0,%1,%2,%3}, [%4];"
                 : "=r"(r0), "=r"(r1), "=r"(r2), "=r"(r3) : "r"(a));
}
__device__ __forceinline__ void mmabf(float* c, const uint32_t* a, const uint32_t* b) {
    asm volatile(
        "mma.sync.aligned.m16n8k16.row.col.f32.bf16.bf16.f32 "
        "{%0,%1,%2,%3}, {%4,%5,%6,%7}, {%8,%9}, {%0,%1,%2,%3};"
        : "+f"(c[0]), "+f"(c[1]), "+f"(c[2]), "+f"(c[3])
        : "r"(a[0]), "r"(a[1]), "r"(a[2]), "r"(a[3]), "r"(b[0]), "r"(b[1]));
}
__device__ __forceinline__ void split2(float v, bf16& h, bf16& l) {
    h = __float2bfloat16(v);
    l = __float2bfloat16(v - __bfloat162float(h));
}
__device__ __forceinline__ float softplusf(float x) {
    return (x > 20.f) ? x : log1pf(expf(x));
}

// ---------------- tensor GEMM: C[256,N] = epi([A1|A2] @ B^T + bias), 3-term bf16 split ----
struct TG {
    const bf16 *A1hi, *A1lo, *A2hi, *A2lo;
    const bf16 *Bhi, *Blo;
    const float* bias;
    float* C;            // epi 0
    bf16 *Chi, *Clo;     // epi 1
    float *o_m, *o_s, *o_z;   // epi 2
    const float* eps;         // epi 2 (posterior)
    bf16 *zhi, *zlo;          // epi 2 (posterior)
    long lda1, lda2, ldb, ldo;
    int K1, K, Ntiles, ldc, ldch, epi;
};

constexpr int ROW_B = 80;     // padded smem row (bytes) for 32 bf16
constexpr int NSTAGE = 3;

template<int NT, int BM, int BN, int WRM, int WRN>
__global__ __launch_bounds__(NT, (NT == 256 ? 2 : 1)) void tgemm_kernel(TG p0, TG p1, TG p2, TG p3) {
    constexpr int NA = (BM / WRM) / 16;
    constexpr int NB = (BN / WRN) / 16;
    constexpr int A_PART = BM * ROW_B;
    constexpr int B_PART = BN * ROW_B;
    constexpr int STAGE  = 2 * (A_PART + B_PART);

    TG p = (blockIdx.z == 0) ? p0 : ((blockIdx.z == 1) ? p1 : ((blockIdx.z == 2) ? p2 : p3));
    if ((int)blockIdx.y >= p.Ntiles) return;

    extern __shared__ char smem[];
    const uint32_t sb = smem_u32(smem);
    const int tid = threadIdx.x, wid = tid >> 5, lane = tid & 31;
    const int m0 = blockIdx.x * BM, n0 = blockIdx.y * BN;
    const int wm = (wid % WRM) * (BM / WRM), wn = (wid / WRM) * (BN / WRN);

    auto loadChunk = [&](int c) {
        uint32_t stg = sb + (c % NSTAGE) * STAGE;
        long koff = (long)c * 32;
        const bf16 *ah, *al; long lda;
        if (koff < p.K1) { ah = p.A1hi; al = p.A1lo; lda = p.lda1; }
        else             { ah = p.A2hi; al = p.A2lo; lda = p.lda2; koff -= p.K1; }
        const bf16* a_hi = ah + (long)m0 * lda + koff;
        const bf16* a_lo = al + (long)m0 * lda + koff;
        const bf16* b_hi = p.Bhi + (long)n0 * p.ldb + (long)c * 32;
        const bf16* b_lo = p.Blo + (long)n0 * p.ldb + (long)c * 32;
#pragma unroll
        for (int o = tid; o < (BM + BN) * 4; o += NT) {
            int row = o >> 2, seg = o & 3;
            if (row < BM) {
                cpa16(stg + row * ROW_B + seg * 16,          a_hi + (long)row * lda + seg * 8);
                cpa16(stg + A_PART + row * ROW_B + seg * 16, a_lo + (long)row * lda + seg * 8);
            } else {
                int br = row - BM;
                cpa16(stg + 2 * A_PART + br * ROW_B + seg * 16,
                      b_hi + (long)br * p.ldb + seg * 8);
                cpa16(stg + 2 * A_PART + B_PART + br * ROW_B + seg * 16,
                      b_lo + (long)br * p.ldb + seg * 8);
            }
        }
        asm volatile("cp.async.commit_group;" ::: "memory");
    };

    float acc[NA][2 * NB][4];
#pragma unroll
    for (int i = 0; i < NA; i++)
#pragma unroll
        for (int j = 0; j < 2 * NB; j++)
#pragma unroll
            for (int k = 0; k < 4; k++) acc[i][j][k] = 0.f;

    const int nch = p.K >> 5;
    loadChunk(0);
    loadChunk(1);
    for (int c = 0; c < nch; c++) {
        asm volatile("cp.async.wait_group 1;" ::: "memory");   // chunk c resident
        __syncthreads();                                       // all warps done with c-1
        if (c + 2 < nch) loadChunk(c + 2);                     // overwrites stage of c-1: safe

        const uint32_t stg = sb + (c % NSTAGE) * STAGE;
#pragma unroll
        for (int kk = 0; kk < 2; kk++) {
            uint32_t Ah[NA][4], Al[NA][4], Bh[NB][4], Bl[NB][4];
#pragma unroll
            for (int mi = 0; mi < NA; mi++) {
                int row = wm + 16 * mi + (lane & 15);
                uint32_t ad = stg + row * ROW_B + kk * 32 + ((lane >> 4) << 4);
                ldsm4(Ah[mi][0], Ah[mi][1], Ah[mi][2], Ah[mi][3], ad);
                ldsm4(Al[mi][0], Al[mi][1], Al[mi][2], Al[mi][3], ad + A_PART);
            }
#pragma unroll
            for (int pp = 0; pp < NB; pp++) {
                int row = wn + 16 * pp + ((lane >> 4) << 3) + (lane & 7);
                uint32_t bd = stg + 2 * A_PART + row * ROW_B + kk * 32 + (((lane >> 3) & 1) << 4);
                ldsm4(Bh[pp][0], Bh[pp][1], Bh[pp][2], Bh[pp][3], bd);
                ldsm4(Bl[pp][0], Bl[pp][1], Bl[pp][2], Bl[pp][3], bd + B_PART);
            }
#pragma unroll
            for (int mi = 0; mi < NA; mi++)
#pragma unroll
                for (int pp = 0; pp < NB; pp++)
#pragma unroll
                    for (int tt = 0; tt < 2; tt++) {
                        float* ca = acc[mi][2 * pp + tt];
                        mmabf(ca, Ah[mi], &Bh[pp][2 * tt]);
                        mmabf(ca, Ah[mi], &Bl[pp][2 * tt]);
                        mmabf(ca, Al[mi], &Bh[pp][2 * tt]);
                    }
        }
    }

    // ---- epilogue ----
    const int mg = m0 + wm, ng = n0 + wn;
#pragma unroll
    for (int mi = 0; mi < NA; mi++) {
        int r = mg + 16 * mi + (lane >> 2);
#pragma unroll
        for (int nj = 0; nj < 2 * NB; nj++) {
            int cg = ng + 8 * nj + 2 * (lane & 3);
            float b0 = p.bias[cg], b1 = p.bias[cg + 1];
            float v00 = acc[mi][nj][0] + b0, v01 = acc[mi][nj][1] + b1;
            float v10 = acc[mi][nj][2] + b0, v11 = acc[mi][nj][3] + b1;
            if (p.epi == 1) {
                v00 = fmaxf(v00, 0.f); v01 = fmaxf(v01, 0.f);
                v10 = fmaxf(v10, 0.f); v11 = fmaxf(v11, 0.f);
                __nv_bfloat162 h2, l2;
                split2(v00, h2.x, l2.x); split2(v01, h2.y, l2.y);
                *(__nv_bfloat162*)(p.Chi + (long)r * p.ldch + cg) = h2;
                *(__nv_bfloat162*)(p.Clo + (long)r * p.ldch + cg) = l2;
                split2(v10, h2.x, l2.x); split2(v11, h2.y, l2.y);
                *(__nv_bfloat162*)(p.Chi + (long)(r + 8) * p.ldch + cg) = h2;
                *(__nv_bfloat162*)(p.Clo + (long)(r + 8) * p.ldch + cg) = l2;
            } else if (p.epi == 0) {
                float2 f2;
                f2.x = v00; f2.y = v01;
                *(float2*)(p.C + (long)r * p.ldc + cg) = f2;
                f2.x = v10; f2.y = v11;
                *(float2*)(p.C + (long)(r + 8) * p.ldc + cg) = f2;
            } else {
                int j = cg >> 1;
#pragma unroll
                for (int hh = 0; hh < 2; hh++) {
                    int rr = r + 8 * hh;
                    float mean = hh ? v10 : v00;
                    float sraw = hh ? v11 : v01;
                    float s = softplusf(sraw) + 0.1f;
                    long o = (long)rr * p.ldo + j;
                    p.o_m[o] = mean;
                    p.o_s[o] = s;
                    if (p.o_z) {
                        float zv = fmaf(s, p.eps[o], mean);
                        p.o_z[o] = zv;
                        split2(zv, p.zhi[rr * STOn + j], p.zlo[rr * STOn + j]);
                    }
                }
            }
        }
    }
}

constexpr int SMEM_BIG   = NSTAGE * 2 * (128 * ROW_B + 128 * ROW_B);  // 122880 (1 CTA/SM)
constexpr int SMEM_SMALL = NSTAGE * 2 * (64 * ROW_B + 64 * ROW_B);    // 61440  (2 CTA/SM)

// ---------------- GRU gate combine (gh = g_gh + g_gh2 split-K partials) ----------------
__global__ __launch_bounds__(256) void gru_kernel(float* __restrict__ hout) {
    int idx = blockIdx.x * blockDim.x + threadIdx.x;
    int b = idx >> 9;
    int d = (idx & 511) << 2;
    const float* gi  = g_gi  + (long)b * G3 + d;
    const float* gh  = g_gh  + (long)b * G3 + d;
    const float* gh2 = g_gh2 + (long)b * G3 + d;
    float4 ir  = *(const float4*)(gi);
    float4 iu  = *(const float4*)(gi + DETn);
    float4 in_ = *(const float4*)(gi + 2 * DETn);
    float4 hr  = *(const float4*)(gh);
    float4 hu  = *(const float4*)(gh + DETn);
    float4 hn  = *(const float4*)(gh + 2 * DETn);
    float4 hr2 = *(const float4*)(gh2);
    float4 hu2 = *(const float4*)(gh2 + DETn);
    float4 hn2 = *(const float4*)(gh2 + 2 * DETn);
    hr.x += hr2.x; hr.y += hr2.y; hr.z += hr2.z; hr.w += hr2.w;
    hu.x += hu2.x; hu.y += hu2.y; hu.z += hu2.z; hu.w += hu2.w;
    hn.x += hn2.x; hn.y += hn2.y; hn.z += hn2.z; hn.w += hn2.w;
    float4 hp  = *(const float4*)(g_h + (long)b * DETn + d);
    float4 hs;
#define GRUC(X) { \
    float r = 1.f / (1.f + expf(-(ir.X + hr.X))); \
    float u = 1.f / (1.f + expf(-(iu.X + hu.X))); \
    float n = tanhf(in_.X + r * hn.X);            \
    hs.X = (1.f - u) * n + u * hp.X; }
    GRUC(x) GRUC(y) GRUC(z) GRUC(w)
#undef GRUC
    *(float4*)(g_h + (long)b * DETn + d) = hs;
    *(float4*)(hout + (long)b * (Tt * DETn) + d) = hs;
    long o = (long)b * DETn + d;
#pragma unroll
    for (int j = 0; j < 4; j++) {
        float v = (&hs.x)[j];
        split2(v, g_h_hi[o + j], g_h_lo[o + j]);
    }
}

// ---------------- combine L4 split-K partials: relu(sum + bias) -> hi/lo ----------------
__global__ __launch_bounds__(256) void combine_pf_kernel(
    const float* __restrict__ b_post, const float* __restrict__ b_prior) {
    int idx = blockIdx.x * blockDim.x + threadIdx.x;   // over Bb*HIDn/4
    long o = (long)idx << 2;
    int n = (idx & 255) << 2;                           // HIDn/4 = 256
    float4 p0 = *(const float4*)(g_pfr0 + o);
    float4 p1 = *(const float4*)(g_pfr1 + o);
    float4 r0 = *(const float4*)(g_rfr0 + o);
    float4 r1 = *(const float4*)(g_rfr1 + o);
    float4 bp = *(const float4*)(b_post + n);
    float4 br = *(const float4*)(b_prior + n);
#pragma unroll
    for (int j = 0; j < 4; j++) {
        float pv = fmaxf((&p0.x)[j] + (&p1.x)[j] + (&bp.x)[j], 0.f);
        float rv = fmaxf((&r0.x)[j] + (&r1.x)[j] + (&br.x)[j], 0.f);
        split2(pv, g_pf_hi[o + j], g_pf_lo[o + j]);
        split2(rv, g_rf_hi[o + j], g_rf_lo[o + j]);
    }
}

// ---------------- merged prep: zero + elementwise splits + bias interleave ----------------
struct SplitJob { const float* src; bf16* hi; bf16* lo; long n; };

__global__ __launch_bounds__(256) void prep_split_kernel(
    SplitJob j0, SplitJob j1, SplitJob j2, SplitJob j3,
    const float* bpm, const float* bqm) {
    long stride = (long)gridDim.x * blockDim.x;
    long gt = (long)blockIdx.x * blockDim.x + threadIdx.x;
    for (long i = gt; i < Bb * DETn; i += stride) {
        g_h[i] = 0.f;
        g_h_hi[i] = __float2bfloat16(0.f);
        g_h_lo[i] = __float2bfloat16(0.f);
    }
    for (long i = gt; i < Bb * STOn; i += stride) {
        g_z_hi[i] = __float2bfloat16(0.f);
        g_z_lo[i] = __float2bfloat16(0.f);
    }
    for (long i = gt; i < 512; i += stride) {
        int c = (int)(i >> 1) + ((int)i & 1) * 256;
        g_bpm_int[i] = bpm[c];
        g_bqm_int[i] = bqm[c];
    }
    SplitJob jobs[4] = {j0, j1, j2, j3};
#pragma unroll
    for (int jj = 0; jj < 4; jj++) {
        SplitJob j = jobs[jj];
        for (long i = gt; i < j.n; i += stride)
            split2(j.src[i], j.hi[i], j.lo[i]);
    }
}

// ---------------- merged prep: transposed splits (optionally column-interleaved) --------
struct TJob { const float* src; bf16* hi; bf16* lo; int R, C, tileEnd, ilv; };

__global__ __launch_bounds__(256) void prep_tsplit_kernel(
    TJob a, TJob b, TJob c, TJob d, TJob e) {
    __shared__ float t[32][33];
    int bid = blockIdx.x;
    TJob j; int tileBase;
    if      (bid < a.tileEnd) { j = a; tileBase = 0; }
    else if (bid < b.tileEnd) { j = b; tileBase = a.tileEnd; }
    else if (bid < c.tileEnd) { j = c; tileBase = b.tileEnd; }
    else if (bid < d.tileEnd) { j = d; tileBase = c.tileEnd; }
    else                      { j = e; tileBase = d.tileEnd; }
    int tile = bid - tileBase;
    int tiles_x = j.C / 32;
    int c0 = (tile % tiles_x) * 32;
    int r0 = (tile / tiles_x) * 32;
    int tx = threadIdx.x & 31, ty = threadIdx.x >> 5;
    for (int i = ty; i < 32; i += 8)
        t[i][tx] = j.src[(long)(r0 + i) * j.C + c0 + tx];
    __syncthreads();
    for (int i = ty; i < 32; i += 8) {
        float v = t[tx][i];
        int cidx = c0 + i;
        int drow = j.ilv ? ((cidx < 256) ? 2 * cidx : 2 * (cidx - 256) + 1) : cidx;
        long o = (long)drow * j.R + r0 + tx;
        split2(v, j.hi[o], j.lo[o]);
    }
}

// ---------------- host orchestration ----------------
static void* sym(const void* s) { void* p; cudaGetSymbolAddress(&p, s); return p; }

extern "C" void kernel_launch(void* const* d_in, const int* in_sizes, int n_in,
                              void* d_out, int out_size) {
    const float* obs        = (const float*)d_in[0];
    const float* actions    = (const float*)d_in[1];
    const float* noise      = (const float*)d_in[4];
    const float* W_rnn      = (const float*)d_in[5];
    const float* b_rnn      = (const float*)d_in[6];
    const float* Wih        = (const float*)d_in[7];
    const float* Whh        = (const float*)d_in[8];
    const float* bih        = (const float*)d_in[9];
    const float* bhh        = (const float*)d_in[10];
    const float* W_post_in  = (const float*)d_in[11];
    const float* b_post_in  = (const float*)d_in[12];
    const float* W_post_ms  = (const float*)d_in[13];
    const float* b_post_ms  = (const float*)d_in[14];
    const float* W_prior_in = (const float*)d_in[15];
    const float* b_prior_in = (const float*)d_in[16];
    const float* W_prior_ms = (const float*)d_in[17];
    const float* b_prior_ms = (const float*)d_in[18];
    float* out = (float*)d_out;

    cudaFuncSetAttribute(tgemm_kernel<512, 128, 128, 4, 4>,
                         cudaFuncAttributeMaxDynamicSharedMemorySize, SMEM_BIG);
    cudaFuncSetAttribute(tgemm_kernel<256, 64, 64, 2, 4>,
                         cudaFuncAttributeMaxDynamicSharedMemorySize, SMEM_SMALL);

    bf16 *Bhh_hi = (bf16*)sym(g_Bhh_hi), *Bhh_lo = (bf16*)sym(g_Bhh_lo);
    bf16 *Bih_hi = (bf16*)sym(g_Bih_hi), *Bih_lo = (bf16*)sym(g_Bih_lo);
    bf16 *Brnn_hi = (bf16*)sym(g_Brnn_hi), *Brnn_lo = (bf16*)sym(g_Brnn_lo);
    bf16 *Bpo_hi = (bf16*)sym(g_Bpo_hi), *Bpo_lo = (bf16*)sym(g_Bpo_lo);
    bf16 *Bpr_hi = (bf16*)sym(g_Bpr_hi), *Bpr_lo = (bf16*)sym(g_Bpr_lo);
    bf16 *Bpm_hi = (bf16*)sym(g_Bpm_hi), *Bpm_lo = (bf16*)sym(g_Bpm_lo);
    bf16 *Bqm_hi = (bf16*)sym(g_Bqm_hi), *Bqm_lo = (bf16*)sym(g_Bqm_lo);
    float *bpm_i = (float*)sym(g_bpm_int), *bqm_i = (float*)sym(g_bqm_int);
    float *zbias = (float*)sym(g_zbias);
    bf16 *obs_hi = (bf16*)sym(g_obs_hi), *obs_lo = (bf16*)sym(g_obs_lo);
    bf16 *act_hi = (bf16*)sym(g_act_hi), *act_lo = (bf16*)sym(g_act_lo);
    bf16 *zact   = (bf16*)sym(g_zact);
    bf16 *h_hi = (bf16*)sym(g_h_hi), *h_lo = (bf16*)sym(g_h_lo);
    bf16 *z_hi = (bf16*)sym(g_z_hi), *z_lo = (bf16*)sym(g_z_lo);
    bf16 *rn_hi = (bf16*)sym(g_rn_hi), *rn_lo = (bf16*)sym(g_rn_lo);
    bf16 *pf_hi = (bf16*)sym(g_pf_hi), *pf_lo = (bf16*)sym(g_pf_lo);
    bf16 *rf_hi = (bf16*)sym(g_rf_hi), *rf_lo = (bf16*)sym(g_rf_lo);
    float *gi_p = (float*)sym(g_gi), *gh_p = (float*)sym(g_gh), *gh2_p = (float*)sym(g_gh2);
    float *pfr0 = (float*)sym(g_pfr0), *pfr1 = (float*)sym(g_pfr1);
    float *rfr0 = (float*)sym(g_rfr0), *rfr1 = (float*)sym(g_rfr1);

    float* out_h  = out;
    float* out_z  = out_h  + (long)Bb * Tt * DETn;
    float* out_pm = out_z  + (long)Bb * Tt * STOn;
    float* out_ps = out_pm + (long)Bb * Tt * STOn;
    float* out_qm = out_ps + (long)Bb * Tt * STOn;
    float* out_qs = out_qm + (long)Bb * Tt * STOn;

    // ---- prep (2 launches) ----
    {
        SplitJob s0 = {Whh,     Bhh_hi, Bhh_lo, (long)G3 * DETn};
        SplitJob s1 = {Wih,     Bih_hi, Bih_lo, (long)G3 * HIDn};
        SplitJob s2 = {obs,     obs_hi, obs_lo, (long)Bb * Tt * Ee};
        SplitJob s3 = {actions, act_hi, act_lo, (long)Bb * Tt * Aa};
        prep_split_kernel<<<2048, 256>>>(s0, s1, s2, s3, b_post_ms, b_prior_ms);

        int t0 = (320 / 32) * (HIDn / 32);
        int t1 = t0 + (3072 / 32) * (HIDn / 32);
        int t2 = t1 + (DETn / 32) * (HIDn / 32);
        int t3 = t2 + (HIDn / 32) * (512 / 32);
        int t4 = t3 + (HIDn / 32) * (512 / 32);
        TJob a = {W_rnn,      Brnn_hi, Brnn_lo, 320,  HIDn, t0, 0};
        TJob b = {W_post_in,  Bpo_hi,  Bpo_lo,  3072, HIDn, t1, 0};
        TJob c = {W_prior_in, Bpr_hi,  Bpr_lo,  DETn, HIDn, t2, 0};
        TJob d = {W_post_ms,  Bpm_hi,  Bpm_lo,  HIDn, 512,  t3, 1};
        TJob e = {W_prior_ms, Bqm_hi,  Bqm_lo,  HIDn, 512,  t4, 1};
        prep_tsplit_kernel<<<t4, 256>>>(a, b, c, d, e);
    }

    for (int t = 0; t < Tt; t++) {
        // L1: rnn_in = relu([z_prev | a_prev] @ W_rnn + b) -> rn hi/lo
        TG prnn = {};
        prnn.A1hi = z_hi; prnn.A1lo = z_lo; prnn.lda1 = STOn; prnn.K1 = STOn;
        if (t > 0) { prnn.A2hi = act_hi + (long)(t - 1) * Aa; prnn.A2lo = act_lo + (long)(t - 1) * Aa; prnn.lda2 = (long)Tt * Aa; }
        else       { prnn.A2hi = zact; prnn.A2lo = zact; prnn.lda2 = Aa; }
        prnn.Bhi = Brnn_hi; prnn.Blo = Brnn_lo; prnn.ldb = 320;
        prnn.bias = b_rnn; prnn.K = 320; prnn.Ntiles = HIDn / 64;
        prnn.epi = 1; prnn.Chi = rn_hi; prnn.Clo = rn_lo; prnn.ldch = HIDn;
        tgemm_kernel<256, 64, 64, 2, 4><<<dim3(4, HIDn / 64, 1), 256, SMEM_SMALL>>>(prnn, prnn, prnn, prnn);

        // L2 split-K: z0 gh half0 (bias), z1 gh half1 (zero bias), z2 gi. 288 equal tiles.
        TG pg0 = {};
        pg0.A1hi = h_hi; pg0.A1lo = h_lo; pg0.lda1 = DETn; pg0.K1 = 1024;
        pg0.Bhi = Bhh_hi; pg0.Blo = Bhh_lo; pg0.ldb = DETn;
        pg0.bias = bhh; pg0.K = 1024; pg0.Ntiles = G3 / 128;
        pg0.epi = 0; pg0.C = gh_p; pg0.ldc = G3;
        TG pg1 = {};
        pg1.A1hi = h_hi + 1024; pg1.A1lo = h_lo + 1024; pg1.lda1 = DETn; pg1.K1 = 1024;
        pg1.Bhi = Bhh_hi + 1024; pg1.Blo = Bhh_lo + 1024; pg1.ldb = DETn;
        pg1.bias = zbias; pg1.K = 1024; pg1.Ntiles = G3 / 128;
        pg1.epi = 0; pg1.C = gh2_p; pg1.ldc = G3;
        TG pgi = {};
        pgi.A1hi = rn_hi; pgi.A1lo = rn_lo; pgi.lda1 = HIDn; pgi.K1 = HIDn;
        pgi.Bhi = Bih_hi; pgi.Blo = Bih_lo; pgi.ldb = HIDn;
        pgi.bias = bih; pgi.K = HIDn; pgi.Ntiles = G3 / 128;
        pgi.epi = 0; pgi.C = gi_p; pgi.ldc = G3;
        tgemm_kernel<512, 128, 128, 4, 4><<<dim3(2, G3 / 128, 3), 512, SMEM_BIG>>>(pg0, pg1, pgi, pgi);

        // L3: GRU elementwise -> h
        gru_kernel<<<(Bb * DETn / 4) / 256, 256>>>(out_h + (long)t * DETn);

        // L4 split-K x2: z0 po half0 (h[0:1536]) ; z1 po half1 (h[1536:2048]|obs) ;
        //               z2 pr half0 (h[0:1024]) ; z3 pr half1 (h[1024:2048]).
        // 256 CTAs -> 2 CTA/SM on all SMs. Partials fp32; combine adds bias+relu+split.
        TG po0 = {};
        po0.A1hi = h_hi; po0.A1lo = h_lo; po0.lda1 = DETn; po0.K1 = 1536;
        po0.Bhi = Bpo_hi; po0.Blo = Bpo_lo; po0.ldb = 3072;
        po0.bias = zbias; po0.K = 1536; po0.Ntiles = HIDn / 64;
        po0.epi = 0; po0.C = pfr0; po0.ldc = HIDn;
        TG po1 = {};
        po1.A1hi = h_hi + 1536; po1.A1lo = h_lo + 1536; po1.lda1 = DETn; po1.K1 = 512;
        po1.A2hi = obs_hi + (long)t * Ee; po1.A2lo = obs_lo + (long)t * Ee; po1.lda2 = (long)Tt * Ee;
        po1.Bhi = Bpo_hi + 1536; po1.Blo = Bpo_lo + 1536; po1.ldb = 3072;
        po1.bias = zbias; po1.K = 1536; po1.Ntiles = HIDn / 64;
        po1.epi = 0; po1.C = pfr1; po1.ldc = HIDn;
        TG pr0 = {};
        pr0.A1hi = h_hi; pr0.A1lo = h_lo; pr0.lda1 = DETn; pr0.K1 = 1024;
        pr0.Bhi = Bpr_hi; pr0.Blo = Bpr_lo; pr0.ldb = DETn;
        pr0.bias = zbias; pr0.K = 1024; pr0.Ntiles = HIDn / 64;
        pr0.epi = 0; pr0.C = rfr0; pr0.ldc = HIDn;
        TG pr1 = {};
        pr1.A1hi = h_hi + 1024; pr1.A1lo = h_lo + 1024; pr1.lda1 = DETn; pr1.K1 = 1024;
        pr1.Bhi = Bpr_hi + 1024; pr1.Blo = Bpr_lo + 1024; pr1.ldb = DETn;
        pr1.bias = zbias; pr1.K = 1024; pr1.Ntiles = HIDn / 64;
        pr1.epi = 0; pr1.C = rfr1; pr1.ldc = HIDn;
        tgemm_kernel<256, 64, 64, 2, 4><<<dim3(4, HIDn / 64, 4), 256, SMEM_SMALL>>>(po0, po1, pr0, pr1);

        // L4b: combine partials -> pf/rf hi,lo
        combine_pf_kernel<<<(Bb * HIDn / 4) / 256, 256>>>(b_post_in, b_prior_in);

        // L5 (fused with finalize): interleaved ms heads; posterior also rsamples z
        TG qpm = {};
        qpm.A1hi = pf_hi; qpm.A1lo = pf_lo; qpm.lda1 = HIDn; qpm.K1 = HIDn;
        qpm.Bhi = Bpm_hi; qpm.Blo = Bpm_lo; qpm.ldb = HIDn;
        qpm.bias = bpm_i; qpm.K = HIDn; qpm.Ntiles = 512 / 64;
        qpm.epi = 2; qpm.ldo = (long)Tt * STOn;
        qpm.o_m = out_pm + (long)t * STOn; qpm.o_s = out_ps + (long)t * STOn;
        qpm.o_z = out_z + (long)t * STOn; qpm.eps = noise + (long)t * STOn;
        qpm.zhi = z_hi; qpm.zlo = z_lo;
        TG qqm = {};
        qqm.A1hi = rf_hi; qqm.A1lo = rf_lo; qqm.lda1 = HIDn; qqm.K1 = HIDn;
        qqm.Bhi = Bqm_hi; qqm.Blo = Bqm_lo; qqm.ldb = HIDn;
        qqm.bias = bqm_i; qqm.K = HIDn; qqm.Ntiles = 512 / 64;
        qqm.epi = 2; qqm.ldo = (long)Tt * STOn;
        qqm.o_m = out_qm + (long)t * STOn; qqm.o_s = out_qs + (long)t * STOn;
        qqm.o_z = nullptr; qqm.eps = nullptr; qqm.zhi = nullptr; qqm.zlo = nullptr;
        tgemm_kernel<256, 64, 64, 2, 4><<<dim3(4, 512 / 64, 2), 256, SMEM_SMALL>>>(qpm, qqm, qqm, qqm);
    }
}

// round 12
// speedup vs baseline: 1.3758x; 1.2501x over previous
#include <cuda_runtime.h>
#include <cuda_bf16.h>
#include <math.h>
#include <stdint.h>

// ---------------- problem constants ----------------
constexpr int Bb  = 256;
constexpr int Tt  = 64;
constexpr int Aa  = 64;
constexpr int Ee  = 1024;
constexpr int HIDn = 1024;
constexpr int DETn = 2048;
constexpr int STOn = 256;
constexpr int G3  = 3 * DETn;   // 6144

typedef __nv_bfloat16 bf16;

// ======== chunk-tiled layout ========
// Array [R rows, K cols] stored as 4KB blocks: blk = (k/32)*G + (row/64), G = R/64.
// Block = 64 rows x 32 bf16, swizzled:
//   elem(row,k) = blk<<11 | (row&63)<<5 | (((k>>3)&3) ^ ((row>>1)&3))<<3 | (k&7)
__host__ __device__ __forceinline__ long tidx(int row, int k, int G) {
    return ((long)((k >> 5) * G + (row >> 6)) << 11)
         | (long)((row & 63) << 5)
         | (long)(((((k >> 3) & 3) ^ ((row >> 1) & 3))) << 3)
         | (long)(k & 7);
}

// ---------------- device-global scratch (tiled layouts) ----------------
__device__ __align__(256) bf16 g_Bhh_hi [G3 * DETn],  g_Bhh_lo [G3 * DETn];   // G=96
__device__ __align__(256) bf16 g_Bih_hi [G3 * HIDn],  g_Bih_lo [G3 * HIDn];   // G=96
__device__ __align__(256) bf16 g_Brnn_hi[HIDn * 320], g_Brnn_lo[HIDn * 320];  // G=16
__device__ __align__(256) bf16 g_Bpo_hi [HIDn * 3072],g_Bpo_lo [HIDn * 3072]; // G=16
__device__ __align__(256) bf16 g_Bpr_hi [HIDn * DETn],g_Bpr_lo [HIDn * DETn]; // G=16
__device__ __align__(256) bf16 g_Bpm_hi [512 * HIDn], g_Bpm_lo [512 * HIDn];  // G=8, interleaved
__device__ __align__(256) bf16 g_Bqm_hi [512 * HIDn], g_Bqm_lo [512 * HIDn];  // G=8, interleaved
__device__ __align__(256) float g_bpm_int[512], g_bqm_int[512];
__device__ __align__(256) float g_zbias[G3];                                  // zeros
__device__ __align__(256) bf16 g_obs_hi[Bb * Tt * Ee], g_obs_lo[Bb * Tt * Ee]; // per-t, G=4
__device__ __align__(256) bf16 g_act_hi[Bb * Tt * Aa], g_act_lo[Bb * Tt * Aa]; // per-t, G=4
__device__ __align__(256) bf16 g_zact  [Bb * Aa];      // zeros
__device__ __align__(256) float g_h   [Bb * DETn];
__device__ __align__(256) bf16  g_h_hi[Bb * DETn], g_h_lo[Bb * DETn];          // tiled G=4
__device__ __align__(256) bf16  g_z_hi[Bb * STOn], g_z_lo[Bb * STOn];          // tiled G=4
__device__ __align__(256) bf16  g_rn_hi[Bb * HIDn], g_rn_lo[Bb * HIDn];        // tiled G=4
__device__ __align__(256) bf16  g_pf_hi[Bb * HIDn], g_pf_lo[Bb * HIDn];        // tiled G=4
__device__ __align__(256) bf16  g_rf_hi[Bb * HIDn], g_rf_lo[Bb * HIDn];        // tiled G=4
__device__ __align__(256) float g_gi[Bb * G3], g_gh[Bb * G3], g_gh2[Bb * G3];
__device__ __align__(256) float g_pfr0[Bb * HIDn], g_pfr1[Bb * HIDn];
__device__ __align__(256) float g_rfr0[Bb * HIDn], g_rfr1[Bb * HIDn];

// ---------------- helpers ----------------
__device__ __forceinline__ uint32_t smem_u32(const void* p) {
    uint32_t a;
    asm("{ .reg .u64 t; cvta.to.shared.u64 t, %1; cvt.u32.u64 %0, t; }" : "=r"(a) : "l"(p));
    return a;
}
__device__ __forceinline__ void ldsm4(uint32_t& r0, uint32_t& r1, uint32_t& r2, uint32_t& r3,
                                      uint32_t a) {
    asm volatile("ldmatrix.sync.aligned.m8n8.x4.shared.b16 {%0,%1,%2,%3}, [%4];"
                 : "=r"(r0), "=r"(r1), "=r"(r2), "=r"(r3) : "r"(a));
}
__device__ __forceinline__ void mmabf(float* c, const uint32_t* a, const uint32_t* b) {
    asm volatile(
        "mma.sync.aligned.m16n8k16.row.col.f32.bf16.bf16.f32 "
        "{%0,%1,%2,%3}, {%4,%5,%6,%7}, {%8,%9}, {%0,%1,%2,%3};"
        : "+f"(c[0]), "+f"(c[1]), "+f"(c[2]), "+f"(c[3])
        : "r"(a[0]), "r"(a[1]), "r"(a[2]), "r"(a[3]), "r"(b[0]), "r"(b[1]));
}
__device__ __forceinline__ void split2(float v, bf16& h, bf16& l) {
    h = __float2bfloat16(v);
    l = __float2bfloat16(v - __bfloat162float(h));
}
__device__ __forceinline__ float softplusf(float x) {
    return (x > 20.f) ? x : log1pf(expf(x));
}
__device__ __forceinline__ void bulk_cp(uint32_t dst, const void* src, uint32_t bytes,
                                        uint32_t mbar) {
    asm volatile(
        "cp.async.bulk.shared::cluster.global.mbarrier::complete_tx::bytes [%0], [%1], %2, [%3];"
        :: "r"(dst), "l"(src), "r"(bytes), "r"(mbar) : "memory");
}
__device__ __forceinline__ void mbar_init(uint32_t m, uint32_t cnt) {
    asm volatile("mbarrier.init.shared.b64 [%0], %1;" :: "r"(m), "r"(cnt) : "memory");
}
__device__ __forceinline__ void mbar_expect(uint32_t m, uint32_t bytes) {
    asm volatile("mbarrier.arrive.expect_tx.shared.b64 _, [%0], %1;"
                 :: "r"(m), "r"(bytes) : "memory");
}
__device__ __forceinline__ void mbar_wait(uint32_t m, uint32_t parity) {
    asm volatile(
        "{\n\t.reg .pred P;\n\t"
        "WL%=:\n\t"
        "mbarrier.try_wait.parity.acquire.cta.shared::cta.b64 P, [%0], %1, 0x989680;\n\t"
        "@P bra WD%=;\n\t"
        "bra WL%=;\n\t"
        "WD%=:\n\t}"
        :: "r"(m), "r"(parity) : "memory");
}

// ---------------- tensor GEMM (tiled operands, bulk-async loads) ----------------
struct TG {
    const bf16 *A1hi, *A1lo, *A2hi, *A2lo;    // tiled activations (256 rows, G=4)
    const bf16 *Bhi, *Blo;                     // tiled weights, gB groups
    const float* bias;
    float* C;                                  // epi 0 (row-major fp32)
    bf16 *Chi, *Clo;                           // epi 1 (tiled G=4)
    float *o_m, *o_s, *o_z;                    // epi 2
    const float* eps;
    bf16 *zhi, *zlo;                           // epi 2 (tiled G=4)
    long ldo;
    int K1c, nch, gB, Ntiles, ldc, epi;
};

template<int NT, int BM, int BN, int WRM, int WRN>
__global__ __launch_bounds__(NT, (NT == 256 ? 2 : 1)) void tgemm_kernel(TG p0, TG p1, TG p2, TG p3) {
    constexpr int NA = (BM / WRM) / 16;
    constexpr int NB = (BN / WRN) / 16;
    constexpr int ABYTES = BM * 64;
    constexpr int BBYTES = BN * 64;
    constexpr int STAGE  = 2 * (ABYTES + BBYTES);

    TG p = (blockIdx.z == 0) ? p0 : ((blockIdx.z == 1) ? p1 : ((blockIdx.z == 2) ? p2 : p3));
    if ((int)blockIdx.y >= p.Ntiles) return;

    extern __shared__ char smem[];
    const uint32_t sb = smem_u32(smem);
    const int tid = threadIdx.x, wid = tid >> 5, lane = tid & 31;
    const int m0 = blockIdx.x * BM, n0 = blockIdx.y * BN;
    const int wm = (wid % WRM) * (BM / WRM), wn = (wid / WRM) * (BN / WRN);
    const int mt0 = m0 >> 6, nt0 = n0 >> 6;

    auto loadChunk = [&](int c) {
        uint32_t stg = sb + 1024 + (c % 3) * STAGE;
        uint32_t bar = sb + (c % 3) * 8;
        mbar_expect(bar, 2 * (ABYTES + BBYTES));
        int cc = c;
        const bf16 *ah, *al;
        if (cc < p.K1c) { ah = p.A1hi; al = p.A1lo; }
        else            { cc -= p.K1c; ah = p.A2hi; al = p.A2lo; }
        bulk_cp(stg,                       ah + (((long)cc * 4 + mt0) << 11), ABYTES, bar);
        bulk_cp(stg + ABYTES,              al + (((long)cc * 4 + mt0) << 11), ABYTES, bar);
        bulk_cp(stg + 2 * ABYTES,          p.Bhi + (((long)c * p.gB + nt0) << 11), BBYTES, bar);
        bulk_cp(stg + 2 * ABYTES + BBYTES, p.Blo + (((long)c * p.gB + nt0) << 11), BBYTES, bar);
    };

    float acc[NA][2 * NB][4];
#pragma unroll
    for (int i = 0; i < NA; i++)
#pragma unroll
        for (int j = 0; j < 2 * NB; j++)
#pragma unroll
            for (int k = 0; k < 4; k++) acc[i][j][k] = 0.f;

    if (tid == 0) {
        mbar_init(sb + 0, 1);
        mbar_init(sb + 8, 1);
        mbar_init(sb + 16, 1);
    }
    __syncthreads();
    const int nch = p.nch;
    if (tid == 0) {
        int pre = nch < 3 ? nch : 3;
        for (int i = 0; i < pre; i++) loadChunk(i);
    }

    for (int c = 0; c < nch; c++) {
        mbar_wait(sb + (c % 3) * 8, (c / 3) & 1);
        const uint32_t stg = sb + 1024 + (c % 3) * STAGE;
#pragma unroll
        for (int kk = 0; kk < 2; kk++) {
            uint32_t Ah[NA][4], Al[NA][4], Bh[NB][4], Bl[NB][4];
#pragma unroll
            for (int mi = 0; mi < NA; mi++) {
                int row = wm + 16 * mi + (lane & 15);
                int sw = (kk * 2 + (lane >> 4)) ^ ((row >> 1) & 3);
                uint32_t ad = stg + row * 64 + (sw << 4);
                ldsm4(Ah[mi][0], Ah[mi][1], Ah[mi][2], Ah[mi][3], ad);
                ldsm4(Al[mi][0], Al[mi][1], Al[mi][2], Al[mi][3], ad + ABYTES);
            }
#pragma unroll
            for (int pp = 0; pp < NB; pp++) {
                int row = wn + 16 * pp + ((lane >> 4) << 3) + (lane & 7);
                int sw = (kk * 2 + ((lane >> 3) & 1)) ^ ((row >> 1) & 3);
                uint32_t bd = stg + 2 * ABYTES + row * 64 + (sw << 4);
                ldsm4(Bh[pp][0], Bh[pp][1], Bh[pp][2], Bh[pp][3], bd);
                ldsm4(Bl[pp][0], Bl[pp][1], Bl[pp][2], Bl[pp][3], bd + BBYTES);
            }
#pragma unroll
            for (int mi = 0; mi < NA; mi++)
#pragma unroll
                for (int pp = 0; pp < NB; pp++)
#pragma unroll
                    for (int tt = 0; tt < 2; tt++) {
                        float* ca = acc[mi][2 * pp + tt];
                        mmabf(ca, Ah[mi], &Bh[pp][2 * tt]);
                        mmabf(ca, Ah[mi], &Bl[pp][2 * tt]);
                        mmabf(ca, Al[mi], &Bh[pp][2 * tt]);
                    }
        }
        __syncthreads();
        if (tid == 0 && c + 3 < nch) loadChunk(c + 3);
    }

    // ---- epilogue ----
    const int mg = m0 + wm, ng = n0 + wn;
#pragma unroll
    for (int mi = 0; mi < NA; mi++) {
        int r = mg + 16 * mi + (lane >> 2);
#pragma unroll
        for (int nj = 0; nj < 2 * NB; nj++) {
            int cg = ng + 8 * nj + 2 * (lane & 3);
            float b0 = p.bias[cg], b1 = p.bias[cg + 1];
            float v00 = acc[mi][nj][0] + b0, v01 = acc[mi][nj][1] + b1;
            float v10 = acc[mi][nj][2] + b0, v11 = acc[mi][nj][3] + b1;
            if (p.epi == 1) {
                v00 = fmaxf(v00, 0.f); v01 = fmaxf(v01, 0.f);
                v10 = fmaxf(v10, 0.f); v11 = fmaxf(v11, 0.f);
                __nv_bfloat162 h2, l2;
                long o = tidx(r, cg, 4);
                split2(v00, h2.x, l2.x); split2(v01, h2.y, l2.y);
                *(__nv_bfloat162*)(p.Chi + o) = h2;
                *(__nv_bfloat162*)(p.Clo + o) = l2;
                o = tidx(r + 8, cg, 4);
                split2(v10, h2.x, l2.x); split2(v11, h2.y, l2.y);
                *(__nv_bfloat162*)(p.Chi + o) = h2;
                *(__nv_bfloat162*)(p.Clo + o) = l2;
            } else if (p.epi == 0) {
                float2 f2;
                f2.x = v00; f2.y = v01;
                *(float2*)(p.C + (long)r * p.ldc + cg) = f2;
                f2.x = v10; f2.y = v11;
                *(float2*)(p.C + (long)(r + 8) * p.ldc + cg) = f2;
            } else {
                int j = cg >> 1;
#pragma unroll
                for (int hh = 0; hh < 2; hh++) {
                    int rr = r + 8 * hh;
                    float mean = hh ? v10 : v00;
                    float sraw = hh ? v11 : v01;
                    float s = softplusf(sraw) + 0.1f;
                    long o = (long)rr * p.ldo + j;
                    p.o_m[o] = mean;
                    p.o_s[o] = s;
                    if (p.o_z) {
                        float zv = fmaf(s, p.eps[o], mean);
                        p.o_z[o] = zv;
                        long zo = tidx(rr, j, 4);
                        bf16 zh = __float2bfloat16(zv);
                        p.zhi[zo] = zh;
                        p.zlo[zo] = __float2bfloat16(zv - __bfloat162float(zh));
                    }
                }
            }
        }
    }
}

constexpr int SMEM_BIG   = 1024 + 3 * 2 * (128 * 64 + 128 * 64);  // 99328
constexpr int SMEM_SMALL = 1024 + 3 * 2 * (64 * 64 + 64 * 64);    // 50176

// ---------------- GRU gate combine (gh = g_gh + g_gh2) ----------------
__global__ __launch_bounds__(256) void gru_kernel(float* __restrict__ hout) {
    int idx = blockIdx.x * blockDim.x + threadIdx.x;
    int b = idx >> 9;
    int d = (idx & 511) << 2;
    const float* gi  = g_gi  + (long)b * G3 + d;
    const float* gh  = g_gh  + (long)b * G3 + d;
    const float* gh2 = g_gh2 + (long)b * G3 + d;
    float4 ir  = *(const float4*)(gi);
    float4 iu  = *(const float4*)(gi + DETn);
    float4 in_ = *(const float4*)(gi + 2 * DETn);
    float4 hr  = *(const float4*)(gh);
    float4 hu  = *(const float4*)(gh + DETn);
    float4 hn  = *(const float4*)(gh + 2 * DETn);
    float4 hr2 = *(const float4*)(gh2);
    float4 hu2 = *(const float4*)(gh2 + DETn);
    float4 hn2 = *(const float4*)(gh2 + 2 * DETn);
    hr.x += hr2.x; hr.y += hr2.y; hr.z += hr2.z; hr.w += hr2.w;
    hu.x += hu2.x; hu.y += hu2.y; hu.z += hu2.z; hu.w += hu2.w;
    hn.x += hn2.x; hn.y += hn2.y; hn.z += hn2.z; hn.w += hn2.w;
    float4 hp  = *(const float4*)(g_h + (long)b * DETn + d);
    float4 hs;
#define GRUC(X) { \
    float r = 1.f / (1.f + expf(-(ir.X + hr.X))); \
    float u = 1.f / (1.f + expf(-(iu.X + hu.X))); \
    float n = tanhf(in_.X + r * hn.X);            \
    hs.X = (1.f - u) * n + u * hp.X; }
    GRUC(x) GRUC(y) GRUC(z) GRUC(w)
#undef GRUC
    *(float4*)(g_h + (long)b * DETn + d) = hs;
    *(float4*)(hout + (long)b * (Tt * DETn) + d) = hs;
    long o = tidx(b, d, 4);   // 4 contiguous elems (d % 4 == 0)
#pragma unroll
    for (int j = 0; j < 4; j++) {
        float v = (&hs.x)[j];
        split2(v, g_h_hi[o + j], g_h_lo[o + j]);
    }
}

// ---------------- combine L4 split-K partials -> pf/rf tiled hi/lo ----------------
__global__ __launch_bounds__(256) void combine_pf_kernel(
    const float* __restrict__ b_post, const float* __restrict__ b_prior) {
    int idx = blockIdx.x * blockDim.x + threadIdx.x;
    int row = idx >> 8;
    int n = (idx & 255) << 2;
    long o = (long)idx << 2;
    float4 p0 = *(const float4*)(g_pfr0 + o);
    float4 p1 = *(const float4*)(g_pfr1 + o);
    float4 r0 = *(const float4*)(g_rfr0 + o);
    float4 r1 = *(const float4*)(g_rfr1 + o);
    float4 bp = *(const float4*)(b_post + n);
    float4 br = *(const float4*)(b_prior + n);
    long to = tidx(row, n, 4);
#pragma unroll
    for (int j = 0; j < 4; j++) {
        float pv = fmaxf((&p0.x)[j] + (&p1.x)[j] + (&bp.x)[j], 0.f);
        float rv = fmaxf((&r0.x)[j] + (&r1.x)[j] + (&br.x)[j], 0.f);
        split2(pv, g_pf_hi[to + j], g_pf_lo[to + j]);
        split2(rv, g_rf_hi[to + j], g_rf_lo[to + j]);
    }
}

// ---------------- prep: zero + tiled splits + bias interleave ----------------
struct SplitJob { const float* src; bf16* hi; bf16* lo; long nseg; long tstride; int K, G, mode; };

__global__ __launch_bounds__(256) void prep_split_kernel(
    SplitJob j0, SplitJob j1, SplitJob j2, SplitJob j3,
    const float* bpm, const float* bqm) {
    long stride = (long)gridDim.x * blockDim.x;
    long gt = (long)blockIdx.x * blockDim.x + threadIdx.x;
    for (long i = gt; i < Bb * DETn; i += stride) {
        g_h[i] = 0.f;
        g_h_hi[i] = __float2bfloat16(0.f);
        g_h_lo[i] = __float2bfloat16(0.f);
    }
    for (long i = gt; i < Bb * STOn; i += stride) {
        g_z_hi[i] = __float2bfloat16(0.f);
        g_z_lo[i] = __float2bfloat16(0.f);
    }
    for (long i = gt; i < 512; i += stride) {
        int c = (int)(i >> 1) + ((int)i & 1) * 256;
        g_bpm_int[i] = bpm[c];
        g_bqm_int[i] = bqm[c];
    }
    SplitJob jobs[4] = {j0, j1, j2, j3};
#pragma unroll
    for (int jj = 0; jj < 4; jj++) {
        SplitJob j = jobs[jj];
        int segPerRow = j.K >> 3;
        for (long s = gt; s < j.nseg; s += stride) {
            long row = s / segPerRow;
            int k = (int)(s % segPerRow) << 3;
            const float* src = j.src + row * j.K + k;
            float4 a = *(const float4*)(src);
            float4 b = *(const float4*)(src + 4);
            bf16 h8[8], l8[8];
#pragma unroll
            for (int q = 0; q < 4; q++) split2((&a.x)[q], h8[q], l8[q]);
#pragma unroll
            for (int q = 0; q < 4; q++) split2((&b.x)[q], h8[4 + q], l8[4 + q]);
            long o;
            if (j.mode == 0) {
                o = tidx((int)row, k, j.G);
            } else {
                int bbx = (int)(row / Tt), t = (int)(row % Tt);
                o = (long)t * j.tstride + tidx(bbx, k, 4);
            }
            *(uint4*)(j.hi + o) = *(uint4*)h8;
            *(uint4*)(j.lo + o) = *(uint4*)l8;
        }
    }
}

// ---------------- prep: transposed splits -> tiled B ----------------
struct TJob { const float* src; bf16* hi; bf16* lo; int R, C, tileEnd, ilv; };

__global__ __launch_bounds__(256) void prep_tsplit_kernel(
    TJob a, TJob b, TJob c, TJob d, TJob e) {
    __shared__ float t[32][33];
    int bid = blockIdx.x;
    TJob j; int tileBase;
    if      (bid < a.tileEnd) { j = a; tileBase = 0; }
    else if (bid < b.tileEnd) { j = b; tileBase = a.tileEnd; }
    else if (bid < c.tileEnd) { j = c; tileBase = b.tileEnd; }
    else if (bid < d.tileEnd) { j = d; tileBase = c.tileEnd; }
    else                      { j = e; tileBase = d.tileEnd; }
    int tile = bid - tileBase;
    int tiles_x = j.C / 32;
    int c0 = (tile % tiles_x) * 32;
    int r0 = (tile / tiles_x) * 32;
    int tx = threadIdx.x & 31, ty = threadIdx.x >> 5;
    for (int i = ty; i < 32; i += 8)
        t[i][tx] = j.src[(long)(r0 + i) * j.C + c0 + tx];
    __syncthreads();
    int G = (j.ilv ? 512 : j.C) / 64;
    for (int i = ty; i < 32; i += 8) {
        float v = t[tx][i];
        int cidx = c0 + i;
        int drow = j.ilv ? ((cidx < 256) ? 2 * cidx : 2 * (cidx - 256) + 1) : cidx;
        long o = tidx(drow, r0 + tx, G);
        split2(v, j.hi[o], j.lo[o]);
    }
}

// ---------------- host orchestration ----------------
static void* sym(const void* s) { void* p; cudaGetSymbolAddress(&p, s); return p; }

extern "C" void kernel_launch(void* const* d_in, const int* in_sizes, int n_in,
                              void* d_out, int out_size) {
    const float* obs        = (const float*)d_in[0];
    const float* actions    = (const float*)d_in[1];
    const float* noise      = (const float*)d_in[4];
    const float* W_rnn      = (const float*)d_in[5];
    const float* b_rnn      = (const float*)d_in[6];
    const float* Wih        = (const float*)d_in[7];
    const float* Whh        = (const float*)d_in[8];
    const float* bih        = (const float*)d_in[9];
    const float* bhh        = (const float*)d_in[10];
    const float* W_post_in  = (const float*)d_in[11];
    const float* b_post_in  = (const float*)d_in[12];
    const float* W_post_ms  = (const float*)d_in[13];
    const float* b_post_ms  = (const float*)d_in[14];
    const float* W_prior_in = (const float*)d_in[15];
    const float* b_prior_in = (const float*)d_in[16];
    const float* W_prior_ms = (const float*)d_in[17];
    const float* b_prior_ms = (const float*)d_in[18];
    float* out = (float*)d_out;

    cudaFuncSetAttribute(tgemm_kernel<512, 128, 128, 4, 4>,
                         cudaFuncAttributeMaxDynamicSharedMemorySize, SMEM_BIG);
    cudaFuncSetAttribute(tgemm_kernel<256, 64, 64, 2, 4>,
                         cudaFuncAttributeMaxDynamicSharedMemorySize, SMEM_SMALL);

    bf16 *Bhh_hi = (bf16*)sym(g_Bhh_hi), *Bhh_lo = (bf16*)sym(g_Bhh_lo);
    bf16 *Bih_hi = (bf16*)sym(g_Bih_hi), *Bih_lo = (bf16*)sym(g_Bih_lo);
    bf16 *Brnn_hi = (bf16*)sym(g_Brnn_hi), *Brnn_lo = (bf16*)sym(g_Brnn_lo);
    bf16 *Bpo_hi = (bf16*)sym(g_Bpo_hi), *Bpo_lo = (bf16*)sym(g_Bpo_lo);
    bf16 *Bpr_hi = (bf16*)sym(g_Bpr_hi), *Bpr_lo = (bf16*)sym(g_Bpr_lo);
    bf16 *Bpm_hi = (bf16*)sym(g_Bpm_hi), *Bpm_lo = (bf16*)sym(g_Bpm_lo);
    bf16 *Bqm_hi = (bf16*)sym(g_Bqm_hi), *Bqm_lo = (bf16*)sym(g_Bqm_lo);
    float *bpm_i = (float*)sym(g_bpm_int), *bqm_i = (float*)sym(g_bqm_int);
    float *zbias = (float*)sym(g_zbias);
    bf16 *obs_hi = (bf16*)sym(g_obs_hi), *obs_lo = (bf16*)sym(g_obs_lo);
    bf16 *act_hi = (bf16*)sym(g_act_hi), *act_lo = (bf16*)sym(g_act_lo);
    bf16 *zact   = (bf16*)sym(g_zact);
    bf16 *h_hi = (bf16*)sym(g_h_hi), *h_lo = (bf16*)sym(g_h_lo);
    bf16 *z_hi = (bf16*)sym(g_z_hi), *z_lo = (bf16*)sym(g_z_lo);
    bf16 *rn_hi = (bf16*)sym(g_rn_hi), *rn_lo = (bf16*)sym(g_rn_lo);
    bf16 *pf_hi = (bf16*)sym(g_pf_hi), *pf_lo = (bf16*)sym(g_pf_lo);
    bf16 *rf_hi = (bf16*)sym(g_rf_hi), *rf_lo = (bf16*)sym(g_rf_lo);
    float *gi_p = (float*)sym(g_gi), *gh_p = (float*)sym(g_gh), *gh2_p = (float*)sym(g_gh2);
    float *pfr0 = (float*)sym(g_pfr0), *pfr1 = (float*)sym(g_pfr1);
    float *rfr0 = (float*)sym(g_rfr0), *rfr1 = (float*)sym(g_rfr1);

    float* out_h  = out;
    float* out_z  = out_h  + (long)Bb * Tt * DETn;
    float* out_pm = out_z  + (long)Bb * Tt * STOn;
    float* out_ps = out_pm + (long)Bb * Tt * STOn;
    float* out_qm = out_ps + (long)Bb * Tt * STOn;
    float* out_qs = out_qm + (long)Bb * Tt * STOn;

    // ---- prep (2 launches) ----
    {
        SplitJob s0 = {Whh,     Bhh_hi, Bhh_lo, (long)G3 * DETn / 8, 0, DETn, 96, 0};
        SplitJob s1 = {Wih,     Bih_hi, Bih_lo, (long)G3 * HIDn / 8, 0, HIDn, 96, 0};
        SplitJob s2 = {obs,     obs_hi, obs_lo, (long)Bb * Tt * Ee / 8, (long)Bb * Ee, Ee, 4, 1};
        SplitJob s3 = {actions, act_hi, act_lo, (long)Bb * Tt * Aa / 8, (long)Bb * Aa, Aa, 4, 1};
        prep_split_kernel<<<2048, 256>>>(s0, s1, s2, s3, b_post_ms, b_prior_ms);

        int t0 = (320 / 32) * (HIDn / 32);
        int t1 = t0 + (3072 / 32) * (HIDn / 32);
        int t2 = t1 + (DETn / 32) * (HIDn / 32);
        int t3 = t2 + (HIDn / 32) * (512 / 32);
        int t4 = t3 + (HIDn / 32) * (512 / 32);
        TJob a = {W_rnn,      Brnn_hi, Brnn_lo, 320,  HIDn, t0, 0};
        TJob b = {W_post_in,  Bpo_hi,  Bpo_lo,  3072, HIDn, t1, 0};
        TJob c = {W_prior_in, Bpr_hi,  Bpr_lo,  DETn, HIDn, t2, 0};
        TJob d = {W_post_ms,  Bpm_hi,  Bpm_lo,  HIDn, 512,  t3, 1};
        TJob e = {W_prior_ms, Bqm_hi,  Bqm_lo,  HIDn, 512,  t4, 1};
        prep_tsplit_kernel<<<t4, 256>>>(a, b, c, d, e);
    }

    constexpr long CBLK = 2048;   // elems per (chunk, group) block

    for (int t = 0; t < Tt; t++) {
        // L1: rnn_in = relu([z | a_prev] @ W_rnn + b) -> rn tiled
        TG prnn = {};
        prnn.A1hi = z_hi; prnn.A1lo = z_lo; prnn.K1c = 8;
        if (t > 0) { prnn.A2hi = act_hi + (long)(t - 1) * Bb * Aa; prnn.A2lo = act_lo + (long)(t - 1) * Bb * Aa; }
        else       { prnn.A2hi = zact; prnn.A2lo = zact; }
        prnn.Bhi = Brnn_hi; prnn.Blo = Brnn_lo; prnn.gB = 16;
        prnn.bias = b_rnn; prnn.nch = 10; prnn.Ntiles = HIDn / 64;
        prnn.epi = 1; prnn.Chi = rn_hi; prnn.Clo = rn_lo;
        tgemm_kernel<256, 64, 64, 2, 4><<<dim3(4, HIDn / 64, 1), 256, SMEM_SMALL>>>(prnn, prnn, prnn, prnn);

        // L2 split-K: z0 gh half0 (bhh), z1 gh half1 (zero bias), z2 gi (bih)
        TG pg0 = {};
        pg0.A1hi = h_hi; pg0.A1lo = h_lo; pg0.K1c = 32;
        pg0.Bhi = Bhh_hi; pg0.Blo = Bhh_lo; pg0.gB = 96;
        pg0.bias = bhh; pg0.nch = 32; pg0.Ntiles = G3 / 128;
        pg0.epi = 0; pg0.C = gh_p; pg0.ldc = G3;
        TG pg1 = {};
        pg1.A1hi = h_hi + 32L * 4 * CBLK; pg1.A1lo = h_lo + 32L * 4 * CBLK; pg1.K1c = 32;
        pg1.Bhi = Bhh_hi + 32L * 96 * CBLK; pg1.Blo = Bhh_lo + 32L * 96 * CBLK; pg1.gB = 96;
        pg1.bias = zbias; pg1.nch = 32; pg1.Ntiles = G3 / 128;
        pg1.epi = 0; pg1.C = gh2_p; pg1.ldc = G3;
        TG pgi = {};
        pgi.A1hi = rn_hi; pgi.A1lo = rn_lo; pgi.K1c = 32;
        pgi.Bhi = Bih_hi; pgi.Blo = Bih_lo; pgi.gB = 96;
        pgi.bias = bih; pgi.nch = 32; pgi.Ntiles = G3 / 128;
        pgi.epi = 0; pgi.C = gi_p; pgi.ldc = G3;
        tgemm_kernel<512, 128, 128, 4, 4><<<dim3(2, G3 / 128, 3), 512, SMEM_BIG>>>(pg0, pg1, pgi, pgi);

        // L3: GRU
        gru_kernel<<<(Bb * DETn / 4) / 256, 256>>>(out_h + (long)t * DETn);

        // L4 split-K x2 -> fp32 partials (zero bias; true bias added in combine)
        TG po0 = {};
        po0.A1hi = h_hi; po0.A1lo = h_lo; po0.K1c = 48;
        po0.Bhi = Bpo_hi; po0.Blo = Bpo_lo; po0.gB = 16;
        po0.bias = zbias; po0.nch = 48; po0.Ntiles = HIDn / 64;
        po0.epi = 0; po0.C = pfr0; po0.ldc = HIDn;
        TG po1 = {};
        po1.A1hi = h_hi + 48L * 4 * CBLK; po1.A1lo = h_lo + 48L * 4 * CBLK; po1.K1c = 16;
        po1.A2hi = obs_hi + (long)t * Bb * Ee; po1.A2lo = obs_lo + (long)t * Bb * Ee;
        po1.Bhi = Bpo_hi + 48L * 16 * CBLK; po1.Blo = Bpo_lo + 48L * 16 * CBLK; po1.gB = 16;
        po1.bias = zbias; po1.nch = 48; po1.Ntiles = HIDn / 64;
        po1.epi = 0; po1.C = pfr1; po1.ldc = HIDn;
        TG pr0 = {};
        pr0.A1hi = h_hi; pr0.A1lo = h_lo; pr0.K1c = 32;
        pr0.Bhi = Bpr_hi; pr0.Blo = Bpr_lo; pr0.gB = 16;
        pr0.bias = zbias; pr0.nch = 32; pr0.Ntiles = HIDn / 64;
        pr0.epi = 0; pr0.C = rfr0; pr0.ldc = HIDn;
        TG pr1 = {};
        pr1.A1hi = h_hi + 32L * 4 * CBLK; pr1.A1lo = h_lo + 32L * 4 * CBLK; pr1.K1c = 32;
        pr1.Bhi = Bpr_hi + 32L * 16 * CBLK; pr1.Blo = Bpr_lo + 32L * 16 * CBLK; pr1.gB = 16;
        pr1.bias = zbias; pr1.nch = 32; pr1.Ntiles = HIDn / 64;
        pr1.epi = 0; pr1.C = rfr1; pr1.ldc = HIDn;
        tgemm_kernel<256, 64, 64, 2, 4><<<dim3(4, HIDn / 64, 4), 256, SMEM_SMALL>>>(po0, po1, pr0, pr1);

        // L4b: combine partials -> pf/rf tiled
        combine_pf_kernel<<<(Bb * HIDn / 4) / 256, 256>>>(b_post_in, b_prior_in);

        // L5: interleaved ms heads (fused finalize); posterior rsamples z
        TG qpm = {};
        qpm.A1hi = pf_hi; qpm.A1lo = pf_lo; qpm.K1c = 32;
        qpm.Bhi = Bpm_hi; qpm.Blo = Bpm_lo; qpm.gB = 8;
        qpm.bias = bpm_i; qpm.nch = 32; qpm.Ntiles = 512 / 64;
        qpm.epi = 2; qpm.ldo = (long)Tt * STOn;
        qpm.o_m = out_pm + (long)t * STOn; qpm.o_s = out_ps + (long)t * STOn;
        qpm.o_z = out_z + (long)t * STOn; qpm.eps = noise + (long)t * STOn;
        qpm.zhi = z_hi; qpm.zlo = z_lo;
        TG qqm = {};
        qqm.A1hi = rf_hi; qqm.A1lo = rf_lo; qqm.K1c = 32;
        qqm.Bhi = Bqm_hi; qqm.Blo = Bqm_lo; qqm.gB = 8;
        qqm.bias = bqm_i; qqm.nch = 32; qqm.Ntiles = 512 / 64;
        qqm.epi = 2; qqm.ldo = (long)Tt * STOn;
        qqm.o_m = out_qm + (long)t * STOn; qqm.o_s = out_qs + (long)t * STOn;
        qqm.o_z = nullptr; qqm.eps = nullptr; qqm.zhi = nullptr; qqm.zlo = nullptr;
        tgemm_kernel<256, 64, 64, 2, 4><<<dim3(4, 512 / 64, 2), 256, SMEM_SMALL>>>(qpm, qqm, qqm, qqm);
    }
}

// round 15
// speedup vs baseline: 1.3839x; 1.0059x over previous
#include <cuda_runtime.h>
#include <cuda_bf16.h>
#include <math.h>
#include <stdint.h>

// ---------------- problem constants ----------------
constexpr int Bb  = 256;
constexpr int Tt  = 64;
constexpr int Aa  = 64;
constexpr int Ee  = 1024;
constexpr int HIDn = 1024;
constexpr int DETn = 2048;
constexpr int STOn = 256;
constexpr int G3  = 3 * DETn;   // 6144

typedef __nv_bfloat16 bf16;

// ======== chunk-tiled layout ========
__host__ __device__ __forceinline__ long tidx(int row, int k, int G) {
    return ((long)((k >> 5) * G + (row >> 6)) << 11)
         | (long)((row & 63) << 5)
         | (long)(((((k >> 3) & 3) ^ ((row >> 1) & 3))) << 3)
         | (long)(k & 7);
}

// ---------------- device-global scratch (tiled layouts) ----------------
__device__ __align__(256) bf16 g_Bhh_hi [G3 * DETn],  g_Bhh_lo [G3 * DETn];   // G=96
__device__ __align__(256) bf16 g_Bih_hi [G3 * HIDn],  g_Bih_lo [G3 * HIDn];   // G=96
__device__ __align__(256) bf16 g_Brnn_hi[HIDn * 320], g_Brnn_lo[HIDn * 320];  // G=16
__device__ __align__(256) bf16 g_Bpo_hi [HIDn * 3072],g_Bpo_lo [HIDn * 3072]; // G=16
__device__ __align__(256) bf16 g_Bpr_hi [HIDn * DETn],g_Bpr_lo [HIDn * DETn]; // G=16
__device__ __align__(256) bf16 g_Bpm_hi [512 * HIDn], g_Bpm_lo [512 * HIDn];  // G=8, interleaved
__device__ __align__(256) bf16 g_Bqm_hi [512 * HIDn], g_Bqm_lo [512 * HIDn];  // G=8, interleaved
__device__ __align__(256) float g_bpm_int[512], g_bqm_int[512];
__device__ __align__(256) float g_zbias[G3];                                  // zeros
__device__ __align__(256) bf16 g_obs_hi[Bb * Tt * Ee], g_obs_lo[Bb * Tt * Ee]; // per-t, G=4
__device__ __align__(256) bf16 g_act_hi[Bb * Tt * Aa], g_act_lo[Bb * Tt * Aa]; // per-t, G=4
__device__ __align__(256) bf16 g_zact  [Bb * Aa];      // zeros
__device__ __align__(256) float g_h   [Bb * DETn];
__device__ __align__(256) bf16  g_h_hi[Bb * DETn], g_h_lo[Bb * DETn];          // tiled G=4
__device__ __align__(256) bf16  g_z_hi[Bb * STOn], g_z_lo[Bb * STOn];          // tiled G=4
__device__ __align__(256) bf16  g_rn_hi[Bb * HIDn], g_rn_lo[Bb * HIDn];        // tiled G=4
__device__ __align__(256) bf16  g_pf_hi[Bb * HIDn], g_pf_lo[Bb * HIDn];        // tiled G=4
__device__ __align__(256) bf16  g_rf_hi[Bb * HIDn], g_rf_lo[Bb * HIDn];        // tiled G=4
__device__ __align__(256) float g_gi[Bb * G3], g_gh[Bb * G3], g_gh2[Bb * G3];
__device__ __align__(256) float g_pfr0[Bb * HIDn], g_pfr1[Bb * HIDn];
__device__ __align__(256) float g_rfr0[Bb * HIDn], g_rfr1[Bb * HIDn];

// ---------------- helpers ----------------
__device__ __forceinline__ uint32_t smem_u32(const void* p) {
    uint32_t a;
    asm("{ .reg .u64 t; cvta.to.shared.u64 t, %1; cvt.u32.u64 %0, t; }" : "=r"(a) : "l"(p));
    return a;
}
__device__ __forceinline__ void ldsm4(uint32_t& r0, uint32_t& r1, uint32_t& r2, uint32_t& r3,
                                      uint32_t a) {
    asm volatile("ldmatrix.sync.aligned.m8n8.x4.shared.b16 {%0,%1,%2,%3}, [%4];"
                 : "=r"(r0), "=r"(r1), "=r"(r2), "=r"(r3) : "r"(a));
}
__device__ __forceinline__ void mmabf(float* c, const uint32_t* a, const uint32_t* b) {
    asm volatile(
        "mma.sync.aligned.m16n8k16.row.col.f32.bf16.bf16.f32 "
        "{%0,%1,%2,%3}, {%4,%5,%6,%7}, {%8,%9}, {%0,%1,%2,%3};"
        : "+f"(c[0]), "+f"(c[1]), "+f"(c[2]), "+f"(c[3])
        : "r"(a[0]), "r"(a[1]), "r"(a[2]), "r"(a[3]), "r"(b[0]), "r"(b[1]));
}
__device__ __forceinline__ void split2(float v, bf16& h, bf16& l) {
    h = __float2bfloat16(v);
    l = __float2bfloat16(v - __bfloat162float(h));
}
__device__ __forceinline__ float softplusf(float x) {
    return (x > 20.f) ? x : log1pf(expf(x));
}
__device__ __forceinline__ void bulk_cp(uint32_t dst, const void* src, uint32_t bytes,
                                        uint32_t mbar) {
    asm volatile(
        "cp.async.bulk.shared::cluster.global.mbarrier::complete_tx::bytes [%0], [%1], %2, [%3];"
        :: "r"(dst), "l"(src), "r"(bytes), "r"(mbar) : "memory");
}
__device__ __forceinline__ void mbar_init(uint32_t m, uint32_t cnt) {
    asm volatile("mbarrier.init.shared.b64 [%0], %1;" :: "r"(m), "r"(cnt) : "memory");
}
__device__ __forceinline__ void mbar_expect(uint32_t m, uint32_t bytes) {
    asm volatile("mbarrier.arrive.expect_tx.shared.b64 _, [%0], %1;"
                 :: "r"(m), "r"(bytes) : "memory");
}
__device__ __forceinline__ void mbar_wait(uint32_t m, uint32_t parity) {
    asm volatile(
        "{\n\t.reg .pred P;\n\t"
        "WL%=:\n\t"
        "mbarrier.try_wait.parity.acquire.cta.shared::cta.b64 P, [%0], %1, 0x989680;\n\t"
        "@P bra WD%=;\n\t"
        "bra WL%=;\n\t"
        "WD%=:\n\t}"
        :: "r"(m), "r"(parity) : "memory");
}

// ---------------- tensor GEMM (tiled operands, bulk loads, frag double-buffer) ----------
struct TG {
    const bf16 *A1hi, *A1lo, *A2hi, *A2lo;    // tiled activations (256 rows, G=4)
    const bf16 *Bhi, *Blo;                     // tiled weights, gB groups
    const float* bias;
    float* C;                                  // epi 0 (row-major fp32)
    bf16 *Chi, *Clo;                           // epi 1 (tiled G=4)
    float *o_m, *o_s, *o_z;                    // epi 2
    const float* eps;
    bf16 *zhi, *zlo;                           // epi 2 (tiled G=4)
    long ldo;
    int K1c, nch, gB, Ntiles, ldc, epi;
};

template<int NT, int BM, int BN, int WRM, int WRN>
__global__ __launch_bounds__(NT, (NT == 256 ? 2 : 1)) void tgemm_kernel(TG p0, TG p1, TG p2, TG p3) {
    constexpr int NA = (BM / WRM) / 16;
    constexpr int NB = (BN / WRN) / 16;
    constexpr int ABYTES = BM * 64;
    constexpr int BBYTES = BN * 64;
    constexpr int STAGE  = 2 * (ABYTES + BBYTES);

    TG p = (blockIdx.z == 0) ? p0 : ((blockIdx.z == 1) ? p1 : ((blockIdx.z == 2) ? p2 : p3));
    if ((int)blockIdx.y >= p.Ntiles) return;

    extern __shared__ char smem[];
    const uint32_t sb = smem_u32(smem);
    const int tid = threadIdx.x, wid = tid >> 5, lane = tid & 31;
    const int m0 = blockIdx.x * BM, n0 = blockIdx.y * BN;
    const int wm = (wid % WRM) * (BM / WRM), wn = (wid / WRM) * (BN / WRN);
    const int mt0 = m0 >> 6, nt0 = n0 >> 6;

    auto loadChunk = [&](int c) {
        uint32_t stg = sb + 1024 + (c & 3) * STAGE;
        uint32_t bar = sb + (c & 3) * 8;
        mbar_expect(bar, 2 * (ABYTES + BBYTES));
        int cc = c;
        const bf16 *ah, *al;
        if (cc < p.K1c) { ah = p.A1hi; al = p.A1lo; }
        else            { cc -= p.K1c; ah = p.A2hi; al = p.A2lo; }
        bulk_cp(stg,                       ah + (((long)cc * 4 + mt0) << 11), ABYTES, bar);
        bulk_cp(stg + ABYTES,              al + (((long)cc * 4 + mt0) << 11), ABYTES, bar);
        bulk_cp(stg + 2 * ABYTES,          p.Bhi + (((long)c * p.gB + nt0) << 11), BBYTES, bar);
        bulk_cp(stg + 2 * ABYTES + BBYTES, p.Blo + (((long)c * p.gB + nt0) << 11), BBYTES, bar);
    };

    float acc[NA][2 * NB][4];
#pragma unroll
    for (int i = 0; i < NA; i++)
#pragma unroll
        for (int j = 0; j < 2 * NB; j++)
#pragma unroll
            for (int k = 0; k < 4; k++) acc[i][j][k] = 0.f;

    // two fragment sets for ldsm/mma overlap
    uint32_t Ah[2][NA][4], Al[2][NA][4], Bh[2][NB][4], Bl[2][NB][4];

    auto ldfr = [&](int c, int kk, int bi) {
        const uint32_t stg = sb + 1024 + (c & 3) * STAGE;
#pragma unroll
        for (int mi = 0; mi < NA; mi++) {
            int row = wm + 16 * mi + (lane & 15);
            int sw = (kk * 2 + (lane >> 4)) ^ ((row >> 1) & 3);
            uint32_t ad = stg + row * 64 + (sw << 4);
            ldsm4(Ah[bi][mi][0], Ah[bi][mi][1], Ah[bi][mi][2], Ah[bi][mi][3], ad);
            ldsm4(Al[bi][mi][0], Al[bi][mi][1], Al[bi][mi][2], Al[bi][mi][3], ad + ABYTES);
        }
#pragma unroll
        for (int pp = 0; pp < NB; pp++) {
            int row = wn + 16 * pp + ((lane >> 4) << 3) + (lane & 7);
            int sw = (kk * 2 + ((lane >> 3) & 1)) ^ ((row >> 1) & 3);
            uint32_t bd = stg + 2 * ABYTES + row * 64 + (sw << 4);
            ldsm4(Bh[bi][pp][0], Bh[bi][pp][1], Bh[bi][pp][2], Bh[bi][pp][3], bd);
            ldsm4(Bl[bi][pp][0], Bl[bi][pp][1], Bl[bi][pp][2], Bl[bi][pp][3], bd + BBYTES);
        }
    };
    auto domma = [&](int bi) {
#pragma unroll
        for (int mi = 0; mi < NA; mi++)
#pragma unroll
            for (int pp = 0; pp < NB; pp++)
#pragma unroll
                for (int tt = 0; tt < 2; tt++) {
                    float* ca = acc[mi][2 * pp + tt];
                    mmabf(ca, Ah[bi][mi], &Bh[bi][pp][2 * tt]);
                    mmabf(ca, Ah[bi][mi], &Bl[bi][pp][2 * tt]);
                    mmabf(ca, Al[bi][mi], &Bh[bi][pp][2 * tt]);
                }
    };

    if (tid == 0) {
        mbar_init(sb + 0, 1);
        mbar_init(sb + 8, 1);
        mbar_init(sb + 16, 1);
        mbar_init(sb + 24, 1);
    }
    __syncthreads();
    const int nch = p.nch;
    if (tid == 0) {
        int pre = nch < 4 ? nch : 4;
        for (int i = 0; i < pre; i++) loadChunk(i);
    }

    mbar_wait(sb + 0, 0);
    ldfr(0, 0, 0);

    for (int c = 0; c < nch; c++) {
        ldfr(c, 1, 1);                 // prefetch second half of this chunk
        domma(0);                      // compute first half (overlaps ldsm above)
        if (c + 1 < nch) {
            mbar_wait(sb + ((c + 1) & 3) * 8, ((c + 1) >> 2) & 1);
            ldfr(c + 1, 0, 0);         // prefetch next chunk's first half
        }
        domma(1);                      // compute second half
        __syncthreads();               // all warps done reading stage (c&3)
        if (tid == 0 && c + 4 < nch) loadChunk(c + 4);
    }

    // ---- epilogue ----
    const int mg = m0 + wm, ng = n0 + wn;
#pragma unroll
    for (int mi = 0; mi < NA; mi++) {
        int r = mg + 16 * mi + (lane >> 2);
#pragma unroll
        for (int nj = 0; nj < 2 * NB; nj++) {
            int cg = ng + 8 * nj + 2 * (lane & 3);
            float b0 = p.bias[cg], b1 = p.bias[cg + 1];
            float v00 = acc[mi][nj][0] + b0, v01 = acc[mi][nj][1] + b1;
            float v10 = acc[mi][nj][2] + b0, v11 = acc[mi][nj][3] + b1;
            if (p.epi == 1) {
                v00 = fmaxf(v00, 0.f); v01 = fmaxf(v01, 0.f);
                v10 = fmaxf(v10, 0.f); v11 = fmaxf(v11, 0.f);
                __nv_bfloat162 h2, l2;
                long o = tidx(r, cg, 4);
                split2(v00, h2.x, l2.x); split2(v01, h2.y, l2.y);
                *(__nv_bfloat162*)(p.Chi + o) = h2;
                *(__nv_bfloat162*)(p.Clo + o) = l2;
                o = tidx(r + 8, cg, 4);
                split2(v10, h2.x, l2.x); split2(v11, h2.y, l2.y);
                *(__nv_bfloat162*)(p.Chi + o) = h2;
                *(__nv_bfloat162*)(p.Clo + o) = l2;
            } else if (p.epi == 0) {
                float2 f2;
                f2.x = v00; f2.y = v01;
                *(float2*)(p.C + (long)r * p.ldc + cg) = f2;
                f2.x = v10; f2.y = v11;
                *(float2*)(p.C + (long)(r + 8) * p.ldc + cg) = f2;
            } else {
                int j = cg >> 1;
#pragma unroll
                for (int hh = 0; hh < 2; hh++) {
                    int rr = r + 8 * hh;
                    float mean = hh ? v10 : v00;
                    float sraw = hh ? v11 : v01;
                    float s = softplusf(sraw) + 0.1f;
                    long o = (long)rr * p.ldo + j;
                    p.o_m[o] = mean;
                    p.o_s[o] = s;
                    if (p.o_z) {
                        float zv = fmaf(s, p.eps[o], mean);
                        p.o_z[o] = zv;
                        long zo = tidx(rr, j, 4);
                        bf16 zh = __float2bfloat16(zv);
                        p.zhi[zo] = zh;
                        p.zlo[zo] = __float2bfloat16(zv - __bfloat162float(zh));
                    }
                }
            }
        }
    }
}

constexpr int SMEM_BIG   = 1024 + 4 * 2 * (128 * 64 + 128 * 64);  // 132096
constexpr int SMEM_SMALL = 1024 + 4 * 2 * (64 * 64 + 64 * 64);    // 66560

// ---------------- GRU gate combine (gh = g_gh + g_gh2) ----------------
__global__ __launch_bounds__(256) void gru_kernel(float* __restrict__ hout) {
    int idx = blockIdx.x * blockDim.x + threadIdx.x;
    int b = idx >> 9;
    int d = (idx & 511) << 2;
    const float* gi  = g_gi  + (long)b * G3 + d;
    const float* gh  = g_gh  + (long)b * G3 + d;
    const float* gh2 = g_gh2 + (long)b * G3 + d;
    float4 ir  = *(const float4*)(gi);
    float4 iu  = *(const float4*)(gi + DETn);
    float4 in_ = *(const float4*)(gi + 2 * DETn);
    float4 hr  = *(const float4*)(gh);
    float4 hu  = *(const float4*)(gh + DETn);
    float4 hn  = *(const float4*)(gh + 2 * DETn);
    float4 hr2 = *(const float4*)(gh2);
    float4 hu2 = *(const float4*)(gh2 + DETn);
    float4 hn2 = *(const float4*)(gh2 + 2 * DETn);
    hr.x += hr2.x; hr.y += hr2.y; hr.z += hr2.z; hr.w += hr2.w;
    hu.x += hu2.x; hu.y += hu2.y; hu.z += hu2.z; hu.w += hu2.w;
    hn.x += hn2.x; hn.y += hn2.y; hn.z += hn2.z; hn.w += hn2.w;
    float4 hp  = *(const float4*)(g_h + (long)b * DETn + d);
    float4 hs;
#define GRUC(X) { \
    float r = 1.f / (1.f + expf(-(ir.X + hr.X))); \
    float u = 1.f / (1.f + expf(-(iu.X + hu.X))); \
    float n = tanhf(in_.X + r * hn.X);            \
    hs.X = (1.f - u) * n + u * hp.X; }
    GRUC(x) GRUC(y) GRUC(z) GRUC(w)
#undef GRUC
    *(float4*)(g_h + (long)b * DETn + d) = hs;
    *(float4*)(hout + (long)b * (Tt * DETn) + d) = hs;
    long o = tidx(b, d, 4);
#pragma unroll
    for (int j = 0; j < 4; j++) {
        float v = (&hs.x)[j];
        split2(v, g_h_hi[o + j], g_h_lo[o + j]);
    }
}

// ---------------- combine L4 split-K partials -> pf/rf tiled hi/lo ----------------
__global__ __launch_bounds__(256) void combine_pf_kernel(
    const float* __restrict__ b_post, const float* __restrict__ b_prior) {
    int idx = blockIdx.x * blockDim.x + threadIdx.x;
    int row = idx >> 8;
    int n = (idx & 255) << 2;
    long o = (long)idx << 2;
    float4 p0 = *(const float4*)(g_pfr0 + o);
    float4 p1 = *(const float4*)(g_pfr1 + o);
    float4 r0 = *(const float4*)(g_rfr0 + o);
    float4 r1 = *(const float4*)(g_rfr1 + o);
    float4 bp = *(const float4*)(b_post + n);
    float4 br = *(const float4*)(b_prior + n);
    long to = tidx(row, n, 4);
#pragma unroll
    for (int j = 0; j < 4; j++) {
        float pv = fmaxf((&p0.x)[j] + (&p1.x)[j] + (&bp.x)[j], 0.f);
        float rv = fmaxf((&r0.x)[j] + (&r1.x)[j] + (&br.x)[j], 0.f);
        split2(pv, g_pf_hi[to + j], g_pf_lo[to + j]);
        split2(rv, g_rf_hi[to + j], g_rf_lo[to + j]);
    }
}

// ---------------- prep: zero + tiled splits + bias interleave ----------------
struct SplitJob { const float* src; bf16* hi; bf16* lo; long nseg; long tstride; int K, G, mode; };

__global__ __launch_bounds__(256) void prep_split_kernel(
    SplitJob j0, SplitJob j1, SplitJob j2, SplitJob j3,
    const float* bpm, const float* bqm) {
    long stride = (long)gridDim.x * blockDim.x;
    long gt = (long)blockIdx.x * blockDim.x + threadIdx.x;
    for (long i = gt; i < Bb * DETn; i += stride) {
        g_h[i] = 0.f;
        g_h_hi[i] = __float2bfloat16(0.f);
        g_h_lo[i] = __float2bfloat16(0.f);
    }
    for (long i = gt; i < Bb * STOn; i += stride) {
        g_z_hi[i] = __float2bfloat16(0.f);
        g_z_lo[i] = __float2bfloat16(0.f);
    }
    for (long i = gt; i < 512; i += stride) {
        int c = (int)(i >> 1) + ((int)i & 1) * 256;
        g_bpm_int[i] = bpm[c];
        g_bqm_int[i] = bqm[c];
    }
    SplitJob jobs[4] = {j0, j1, j2, j3};
#pragma unroll
    for (int jj = 0; jj < 4; jj++) {
        SplitJob j = jobs[jj];
        int segPerRow = j.K >> 3;
        for (long s = gt; s < j.nseg; s += stride) {
            long row = s / segPerRow;
            int k = (int)(s % segPerRow) << 3;
            const float* src = j.src + row * j.K + k;
            float4 a = *(const float4*)(src);
            float4 b = *(const float4*)(src + 4);
            bf16 h8[8], l8[8];
#pragma unroll
            for (int q = 0; q < 4; q++) split2((&a.x)[q], h8[q], l8[q]);
#pragma unroll
            for (int q = 0; q < 4; q++) split2((&b.x)[q], h8[4 + q], l8[4 + q]);
            long o;
            if (j.mode == 0) {
                o = tidx((int)row, k, j.G);
            } else {
                int bbx = (int)(row / Tt), t = (int)(row % Tt);
                o = (long)t * j.tstride + tidx(bbx, k, 4);
            }
            *(uint4*)(j.hi + o) = *(uint4*)h8;
            *(uint4*)(j.lo + o) = *(uint4*)l8;
        }
    }
}

// ---------------- prep: transposed splits -> tiled B ----------------
struct TJob { const float* src; bf16* hi; bf16* lo; int R, C, tileEnd, ilv; };

__global__ __launch_bounds__(256) void prep_tsplit_kernel(
    TJob a, TJob b, TJob c, TJob d, TJob e) {
    __shared__ float t[32][33];
    int bid = blockIdx.x;
    TJob j; int tileBase;
    if      (bid < a.tileEnd) { j = a; tileBase = 0; }
    else if (bid < b.tileEnd) { j = b; tileBase = a.tileEnd; }
    else if (bid < c.tileEnd) { j = c; tileBase = b.tileEnd; }
    else if (bid < d.tileEnd) { j = d; tileBase = c.tileEnd; }
    else                      { j = e; tileBase = d.tileEnd; }
    int tile = bid - tileBase;
    int tiles_x = j.C / 32;
    int c0 = (tile % tiles_x) * 32;
    int r0 = (tile / tiles_x) * 32;
    int tx = threadIdx.x & 31, ty = threadIdx.x >> 5;
    for (int i = ty; i < 32; i += 8)
        t[i][tx] = j.src[(long)(r0 + i) * j.C + c0 + tx];
    __syncthreads();
    int G = (j.ilv ? 512 : j.C) / 64;
    for (int i = ty; i < 32; i += 8) {
        float v = t[tx][i];
        int cidx = c0 + i;
        int drow = j.ilv ? ((cidx < 256) ? 2 * cidx : 2 * (cidx - 256) + 1) : cidx;
        long o = tidx(drow, r0 + tx, G);
        split2(v, j.hi[o], j.lo[o]);
    }
}

// ---------------- host orchestration ----------------
static void* sym(const void* s) { void* p; cudaGetSymbolAddress(&p, s); return p; }

extern "C" void kernel_launch(void* const* d_in, const int* in_sizes, int n_in,
                              void* d_out, int out_size) {
    const float* obs        = (const float*)d_in[0];
    const float* actions    = (const float*)d_in[1];
    const float* noise      = (const float*)d_in[4];
    const float* W_rnn      = (const float*)d_in[5];
    const float* b_rnn      = (const float*)d_in[6];
    const float* Wih        = (const float*)d_in[7];
    const float* Whh        = (const float*)d_in[8];
    const float* bih        = (const float*)d_in[9];
    const float* bhh        = (const float*)d_in[10];
    const float* W_post_in  = (const float*)d_in[11];
    const float* b_post_in  = (const float*)d_in[12];
    const float* W_post_ms  = (const float*)d_in[13];
    const float* b_post_ms  = (const float*)d_in[14];
    const float* W_prior_in = (const float*)d_in[15];
    const float* b_prior_in = (const float*)d_in[16];
    const float* W_prior_ms = (const float*)d_in[17];
    const float* b_prior_ms = (const float*)d_in[18];
    float* out = (float*)d_out;

    cudaFuncSetAttribute(tgemm_kernel<512, 128, 128, 4, 4>,
                         cudaFuncAttributeMaxDynamicSharedMemorySize, SMEM_BIG);
    cudaFuncSetAttribute(tgemm_kernel<256, 64, 64, 2, 4>,
                         cudaFuncAttributeMaxDynamicSharedMemorySize, SMEM_SMALL);

    bf16 *Bhh_hi = (bf16*)sym(g_Bhh_hi), *Bhh_lo = (bf16*)sym(g_Bhh_lo);
    bf16 *Bih_hi = (bf16*)sym(g_Bih_hi), *Bih_lo = (bf16*)sym(g_Bih_lo);
    bf16 *Brnn_hi = (bf16*)sym(g_Brnn_hi), *Brnn_lo = (bf16*)sym(g_Brnn_lo);
    bf16 *Bpo_hi = (bf16*)sym(g_Bpo_hi), *Bpo_lo = (bf16*)sym(g_Bpo_lo);
    bf16 *Bpr_hi = (bf16*)sym(g_Bpr_hi), *Bpr_lo = (bf16*)sym(g_Bpr_lo);
    bf16 *Bpm_hi = (bf16*)sym(g_Bpm_hi), *Bpm_lo = (bf16*)sym(g_Bpm_lo);
    bf16 *Bqm_hi = (bf16*)sym(g_Bqm_hi), *Bqm_lo = (bf16*)sym(g_Bqm_lo);
    float *bpm_i = (float*)sym(g_bpm_int), *bqm_i = (float*)sym(g_bqm_int);
    float *zbias = (float*)sym(g_zbias);
    bf16 *obs_hi = (bf16*)sym(g_obs_hi), *obs_lo = (bf16*)sym(g_obs_lo);
    bf16 *act_hi = (bf16*)sym(g_act_hi), *act_lo = (bf16*)sym(g_act_lo);
    bf16 *zact   = (bf16*)sym(g_zact);
    bf16 *h_hi = (bf16*)sym(g_h_hi), *h_lo = (bf16*)sym(g_h_lo);
    bf16 *z_hi = (bf16*)sym(g_z_hi), *z_lo = (bf16*)sym(g_z_lo);
    bf16 *rn_hi = (bf16*)sym(g_rn_hi), *rn_lo = (bf16*)sym(g_rn_lo);
    bf16 *pf_hi = (bf16*)sym(g_pf_hi), *pf_lo = (bf16*)sym(g_pf_lo);
    bf16 *rf_hi = (bf16*)sym(g_rf_hi), *rf_lo = (bf16*)sym(g_rf_lo);
    float *gi_p = (float*)sym(g_gi), *gh_p = (float*)sym(g_gh), *gh2_p = (float*)sym(g_gh2);
    float *pfr0 = (float*)sym(g_pfr0), *pfr1 = (float*)sym(g_pfr1);
    float *rfr0 = (float*)sym(g_rfr0), *rfr1 = (float*)sym(g_rfr1);

    float* out_h  = out;
    float* out_z  = out_h  + (long)Bb * Tt * DETn;
    float* out_pm = out_z  + (long)Bb * Tt * STOn;
    float* out_ps = out_pm + (long)Bb * Tt * STOn;
    float* out_qm = out_ps + (long)Bb * Tt * STOn;
    float* out_qs = out_qm + (long)Bb * Tt * STOn;

    // ---- prep (2 launches) ----
    {
        SplitJob s0 = {Whh,     Bhh_hi, Bhh_lo, (long)G3 * DETn / 8, 0, DETn, 96, 0};
        SplitJob s1 = {Wih,     Bih_hi, Bih_lo, (long)G3 * HIDn / 8, 0, HIDn, 96, 0};
        SplitJob s2 = {obs,     obs_hi, obs_lo, (long)Bb * Tt * Ee / 8, (long)Bb * Ee, Ee, 4, 1};
        SplitJob s3 = {actions, act_hi, act_lo, (long)Bb * Tt * Aa / 8, (long)Bb * Aa, Aa, 4, 1};
        prep_split_kernel<<<2048, 256>>>(s0, s1, s2, s3, b_post_ms, b_prior_ms);

        int t0 = (320 / 32) * (HIDn / 32);
        int t1 = t0 + (3072 / 32) * (HIDn / 32);
        int t2 = t1 + (DETn / 32) * (HIDn / 32);
        int t3 = t2 + (HIDn / 32) * (512 / 32);
        int t4 = t3 + (HIDn / 32) * (512 / 32);
        TJob a = {W_rnn,      Brnn_hi, Brnn_lo, 320,  HIDn, t0, 0};
        TJob b = {W_post_in,  Bpo_hi,  Bpo_lo,  3072, HIDn, t1, 0};
        TJob c = {W_prior_in, Bpr_hi,  Bpr_lo,  DETn, HIDn, t2, 0};
        TJob d = {W_post_ms,  Bpm_hi,  Bpm_lo,  HIDn, 512,  t3, 1};
        TJob e = {W_prior_ms, Bqm_hi,  Bqm_lo,  HIDn, 512,  t4, 1};
        prep_tsplit_kernel<<<t4, 256>>>(a, b, c, d, e);
    }

    constexpr long CBLK = 2048;

    for (int t = 0; t < Tt; t++) {
        // L1: rnn_in = relu([z | a_prev] @ W_rnn + b) -> rn tiled
        TG prnn = {};
        prnn.A1hi = z_hi; prnn.A1lo = z_lo; prnn.K1c = 8;
        if (t > 0) { prnn.A2hi = act_hi + (long)(t - 1) * Bb * Aa; prnn.A2lo = act_lo + (long)(t - 1) * Bb * Aa; }
        else       { prnn.A2hi = zact; prnn.A2lo = zact; }
        prnn.Bhi = Brnn_hi; prnn.Blo = Brnn_lo; prnn.gB = 16;
        prnn.bias = b_rnn; prnn.nch = 10; prnn.Ntiles = HIDn / 64;
        prnn.epi = 1; prnn.Chi = rn_hi; prnn.Clo = rn_lo;
        tgemm_kernel<256, 64, 64, 2, 4><<<dim3(4, HIDn / 64, 1), 256, SMEM_SMALL>>>(prnn, prnn, prnn, prnn);

        // L2 split-K: z0 gh half0 (bhh), z1 gh half1 (zero bias), z2 gi (bih)
        TG pg0 = {};
        pg0.A1hi = h_hi; pg0.A1lo = h_lo; pg0.K1c = 32;
        pg0.Bhi = Bhh_hi; pg0.Blo = Bhh_lo; pg0.gB = 96;
        pg0.bias = bhh; pg0.nch = 32; pg0.Ntiles = G3 / 128;
        pg0.epi = 0; pg0.C = gh_p; pg0.ldc = G3;
        TG pg1 = {};
        pg1.A1hi = h_hi + 32L * 4 * CBLK; pg1.A1lo = h_lo + 32L * 4 * CBLK; pg1.K1c = 32;
        pg1.Bhi = Bhh_hi + 32L * 96 * CBLK; pg1.Blo = Bhh_lo + 32L * 96 * CBLK; pg1.gB = 96;
        pg1.bias = zbias; pg1.nch = 32; pg1.Ntiles = G3 / 128;
        pg1.epi = 0; pg1.C = gh2_p; pg1.ldc = G3;
        TG pgi = {};
        pgi.A1hi = rn_hi; pgi.A1lo = rn_lo; pgi.K1c = 32;
        pgi.Bhi = Bih_hi; pgi.Blo = Bih_lo; pgi.gB = 96;
        pgi.bias = bih; pgi.nch = 32; pgi.Ntiles = G3 / 128;
        pgi.epi = 0; pgi.C = gi_p; pgi.ldc = G3;
        tgemm_kernel<512, 128, 128, 4, 4><<<dim3(2, G3 / 128, 3), 512, SMEM_BIG>>>(pg0, pg1, pgi, pgi);

        // L3: GRU
        gru_kernel<<<(Bb * DETn / 4) / 256, 256>>>(out_h + (long)t * DETn);

        // L4 split-K x2 -> fp32 partials (zero bias; true bias added in combine)
        TG po0 = {};
        po0.A1hi = h_hi; po0.A1lo = h_lo; po0.K1c = 48;
        po0.Bhi = Bpo_hi; po0.Blo = Bpo_lo; po0.gB = 16;
        po0.bias = zbias; po0.nch = 48; po0.Ntiles = HIDn / 64;
        po0.epi = 0; po0.C = pfr0; po0.ldc = HIDn;
        TG po1 = {};
        po1.A1hi = h_hi + 48L * 4 * CBLK; po1.A1lo = h_lo + 48L * 4 * CBLK; po1.K1c = 16;
        po1.A2hi = obs_hi + (long)t * Bb * Ee; po1.A2lo = obs_lo + (long)t * Bb * Ee;
        po1.Bhi = Bpo_hi + 48L * 16 * CBLK; po1.Blo = Bpo_lo + 48L * 16 * CBLK; po1.gB = 16;
        po1.bias = zbias; po1.nch = 48; po1.Ntiles = HIDn / 64;
        po1.epi = 0; po1.C = pfr1; po1.ldc = HIDn;
        TG pr0 = {};
        pr0.A1hi = h_hi; pr0.A1lo = h_lo; pr0.K1c = 32;
        pr0.Bhi = Bpr_hi; pr0.Blo = Bpr_lo; pr0.gB = 16;
        pr0.bias = zbias; pr0.nch = 32; pr0.Ntiles = HIDn / 64;
        pr0.epi = 0; pr0.C = rfr0; pr0.ldc = HIDn;
        TG pr1 = {};
        pr1.A1hi = h_hi + 32L * 4 * CBLK; pr1.A1lo = h_lo + 32L * 4 * CBLK; pr1.K1c = 32;
        pr1.Bhi = Bpr_hi + 32L * 16 * CBLK; pr1.Blo = Bpr_lo + 32L * 16 * CBLK; pr1.gB = 16;
        pr1.bias = zbias; pr1.nch = 32; pr1.Ntiles = HIDn / 64;
        pr1.epi = 0; pr1.C = rfr1; pr1.ldc = HIDn;
        tgemm_kernel<256, 64, 64, 2, 4><<<dim3(4, HIDn / 64, 4), 256, SMEM_SMALL>>>(po0, po1, pr0, pr1);

        // L4b: combine partials -> pf/rf tiled
        combine_pf_kernel<<<(Bb * HIDn / 4) / 256, 256>>>(b_post_in, b_prior_in);

        // L5: interleaved ms heads (fused finalize); posterior rsamples z
        TG qpm = {};
        qpm.A1hi = pf_hi; qpm.A1lo = pf_lo; qpm.K1c = 32;
        qpm.Bhi = Bpm_hi; qpm.Blo = Bpm_lo; qpm.gB = 8;
        qpm.bias = bpm_i; qpm.nch = 32; qpm.Ntiles = 512 / 64;
        qpm.epi = 2; qpm.ldo = (long)Tt * STOn;
        qpm.o_m = out_pm + (long)t * STOn; qpm.o_s = out_ps + (long)t * STOn;
        qpm.o_z = out_z + (long)t * STOn; qpm.eps = noise + (long)t * STOn;
        qpm.zhi = z_hi; qpm.zlo = z_lo;
        TG qqm = {};
        qqm.A1hi = rf_hi; qqm.A1lo = rf_lo; qqm.K1c = 32;
        qqm.Bhi = Bqm_hi; qqm.Blo = Bqm_lo; qqm.gB = 8;
        qqm.bias = bqm_i; qqm.nch = 32; qqm.Ntiles = 512 / 64;
        qqm.epi = 2; qqm.ldo = (long)Tt * STOn;
        qqm.o_m = out_qm + (long)t * STOn; qqm.o_s = out_qs + (long)t * STOn;
        qqm.o_z = nullptr; qqm.eps = nullptr; qqm.zhi = nullptr; qqm.zlo = nullptr;
        tgemm_kernel<256, 64, 64, 2, 4><<<dim3(4, 512 / 64, 2), 256, SMEM_SMALL>>>(qpm, qqm, qqm, qqm);
    }
}